// round 5
// baseline (speedup 1.0000x reference)
#include <cuda_runtime.h>
#include <cuda_bf16.h>
#include <math.h>
#include <stdint.h>

#define T_SEQ 2048
#define CDIM  1024
#define NB    2
#define NH    16
#define HD    64
#define MTOK  (NB * T_SEQ)   // 4096 token rows

// ---------------------------------------------------------------------------
// Scratch (static device globals)
// ---------------------------------------------------------------------------
__device__ __nv_bfloat16 g_xhi[(size_t)MTOK * CDIM];
__device__ __align__(256) uint8_t g_xhi8[(size_t)MTOK * CDIM];
__device__ __align__(256) uint8_t g_xlo8[(size_t)MTOK * CDIM];

__device__ __nv_bfloat16 g_wqh[(size_t)CDIM * CDIM];
__device__ __nv_bfloat16 g_wkh[(size_t)CDIM * CDIM];
__device__ __nv_bfloat16 g_wvh[(size_t)CDIM * CDIM];
__device__ __nv_bfloat16 g_woh[(size_t)CDIM * CDIM];
__device__ __align__(256) uint8_t g_wq8 [(size_t)CDIM * CDIM];
__device__ __align__(256) uint8_t g_wq8l[(size_t)CDIM * CDIM];
__device__ __align__(256) uint8_t g_wk8 [(size_t)CDIM * CDIM];
__device__ __align__(256) uint8_t g_wk8l[(size_t)CDIM * CDIM];
__device__ __align__(256) uint8_t g_wv8 [(size_t)CDIM * CDIM];
__device__ __align__(256) uint8_t g_wv8l[(size_t)CDIM * CDIM];
__device__ __align__(256) uint8_t g_wo8 [(size_t)CDIM * CDIM];
__device__ __align__(256) uint8_t g_wo8l[(size_t)CDIM * CDIM];

__device__ __nv_bfloat16 g_qhi[(size_t)MTOK * CDIM];
__device__ __nv_bfloat16 g_qlo[(size_t)MTOK * CDIM];
__device__ __nv_bfloat16 g_khi[(size_t)MTOK * CDIM];
__device__ __nv_bfloat16 g_klo[(size_t)MTOK * CDIM];
__device__ __nv_bfloat16 g_vhi[(size_t)MTOK * CDIM];
__device__ __nv_bfloat16 g_vlo[(size_t)MTOK * CDIM];

__device__ __nv_bfloat16 g_ahi[(size_t)MTOK * CDIM];
__device__ __align__(256) uint8_t g_ah8[(size_t)MTOK * CDIM];
__device__ __align__(256) uint8_t g_al8[(size_t)MTOK * CDIM];

#define CROSS_SCALE 256.0f
#define CROSS_INV   (1.0f / 256.0f)

// ---------------------------------------------------------------------------
// Helpers
// ---------------------------------------------------------------------------
__device__ __forceinline__ uint32_t smem_u32(const void* p) {
    uint32_t a;
    asm("{ .reg .u64 t; cvta.to.shared.u64 t, %1; cvt.u32.u64 %0, t; }"
        : "=r"(a) : "l"(p));
    return a;
}
__device__ __forceinline__ float ex2f(float x) {
    float y; asm("ex2.approx.ftz.f32 %0, %1;" : "=f"(y) : "f"(x)); return y;
}
__device__ __forceinline__ void ldsm4(uint32_t& r0, uint32_t& r1,
                                      uint32_t& r2, uint32_t& r3, uint32_t addr) {
    asm volatile("ldmatrix.sync.aligned.m8n8.x4.shared.b16 {%0,%1,%2,%3}, [%4];"
                 : "=r"(r0), "=r"(r1), "=r"(r2), "=r"(r3) : "r"(addr));
}
__device__ __forceinline__ void ldsm4t(uint32_t& r0, uint32_t& r1,
                                       uint32_t& r2, uint32_t& r3, uint32_t addr) {
    asm volatile("ldmatrix.sync.aligned.m8n8.x4.trans.shared.b16 {%0,%1,%2,%3}, [%4];"
                 : "=r"(r0), "=r"(r1), "=r"(r2), "=r"(r3) : "r"(addr));
}
__device__ __forceinline__ void mma_bf16(float* c, const uint32_t* a,
                                         uint32_t b0, uint32_t b1) {
    asm volatile(
        "mma.sync.aligned.m16n8k16.row.col.f32.bf16.bf16.f32 "
        "{%0,%1,%2,%3}, {%4,%5,%6,%7}, {%8,%9}, {%0,%1,%2,%3};"
        : "+f"(c[0]), "+f"(c[1]), "+f"(c[2]), "+f"(c[3])
        : "r"(a[0]), "r"(a[1]), "r"(a[2]), "r"(a[3]), "r"(b0), "r"(b1));
}
__device__ __forceinline__ void mma_fp8(float* c, const uint32_t* a,
                                        uint32_t b0, uint32_t b1) {
    asm volatile(
        "mma.sync.aligned.m16n8k32.row.col.f32.e4m3.e4m3.f32 "
        "{%0,%1,%2,%3}, {%4,%5,%6,%7}, {%8,%9}, {%0,%1,%2,%3};"
        : "+f"(c[0]), "+f"(c[1]), "+f"(c[2]), "+f"(c[3])
        : "r"(a[0]), "r"(a[1]), "r"(a[2]), "r"(a[3]), "r"(b0), "r"(b1));
}
__device__ __forceinline__ uint32_t packbf(float lo, float hi) {
    uint32_t d;
    asm("cvt.rn.bf16x2.f32 %0, %1, %2;" : "=r"(d) : "f"(hi), "f"(lo));
    return d;
}
__device__ __forceinline__ uint16_t pack_e4m3(float lo, float hi) {
    uint16_t d;
    asm("cvt.rn.satfinite.e4m3x2.f32 %0, %1, %2;" : "=h"(d) : "f"(hi), "f"(lo));
    return d;
}
__device__ __forceinline__ void split2(float f0, float f1, uint32_t& hp, uint32_t& lp) {
    hp = packbf(f0, f1);
    float h0 = __uint_as_float(hp << 16);
    float h1 = __uint_as_float(hp & 0xffff0000u);
    lp = packbf(f0 - h0, f1 - h1);
}
// bf16-hi + e4m3(f) + e4m3(256*lo)
__device__ __forceinline__ void split_o8(float f0, float f1, uint32_t& hp,
                                         uint16_t& h8, uint16_t& l8) {
    hp = packbf(f0, f1);
    float h0 = __uint_as_float(hp << 16);
    float h1 = __uint_as_float(hp & 0xffff0000u);
    h8 = pack_e4m3(f0, f1);
    l8 = pack_e4m3((f0 - h0) * CROSS_SCALE, (f1 - h1) * CROSS_SCALE);
}

// ---------------------------------------------------------------------------
// fp32 -> {bf16 hi, e4m3(x), e4m3(256*lo)}
// ---------------------------------------------------------------------------
__global__ __launch_bounds__(256) void split3(
    const float* __restrict__ in, __nv_bfloat16* __restrict__ hi,
    uint8_t* __restrict__ h8, uint8_t* __restrict__ l8, int n4)
{
    int i = blockIdx.x * blockDim.x + threadIdx.x;
    const int stride = gridDim.x * blockDim.x;
    for (; i < n4; i += stride) {
        float4 v = *(const float4*)(in + (size_t)i * 4);
        uint32_t h01 = packbf(v.x, v.y);
        uint32_t h23 = packbf(v.z, v.w);
        uint2 hh; hh.x = h01; hh.y = h23;
        *(uint2*)(hi + (size_t)i * 4) = hh;

        uint32_t e = (uint32_t)pack_e4m3(v.x, v.y) |
                     ((uint32_t)pack_e4m3(v.z, v.w) << 16);
        *(uint32_t*)(h8 + (size_t)i * 4) = e;

        float l0 = v.x - __uint_as_float(h01 << 16);
        float l1 = v.y - __uint_as_float(h01 & 0xffff0000u);
        float l2 = v.z - __uint_as_float(h23 << 16);
        float l3 = v.w - __uint_as_float(h23 & 0xffff0000u);
        uint32_t el = (uint32_t)pack_e4m3(l0 * CROSS_SCALE, l1 * CROSS_SCALE) |
                      ((uint32_t)pack_e4m3(l2 * CROSS_SCALE, l3 * CROSS_SCALE) << 16);
        *(uint32_t*)(l8 + (size_t)i * 4) = el;
    }
}

// ---------------------------------------------------------------------------
// GEMM machinery: CTA 128x128, 8 warps (32x64 warp tile), 16KB tiles
// (128 rows x 128B), chunk-XOR swizzle, cp.async double buffer.
// Phase A: 16 fp8 tiles (cross terms, k=128/tile), rescale, Phase B: 16 bf16.
// ---------------------------------------------------------------------------
#define TILEB 16384

__device__ __forceinline__ void stage_bf(
    uint32_t s, const __nv_bfloat16* __restrict__ G, int r0, int koff, int tid)
{
#pragma unroll
    for (int i = 0; i < 4; ++i) {
        int idx = tid + i * 256;
        int r = idx >> 3, c = idx & 7;
        uint32_t sw = r * 128 + ((c ^ (r & 7)) << 4);
        const __nv_bfloat16* g = G + (size_t)(r0 + r) * CDIM + koff + c * 8;
        asm volatile("cp.async.cg.shared.global [%0], [%1], 16;"
                     :: "r"(s + sw), "l"(g));
    }
}
__device__ __forceinline__ void stage_f8(
    uint32_t s, const uint8_t* __restrict__ G, int r0, int koff, int tid)
{
#pragma unroll
    for (int i = 0; i < 4; ++i) {
        int idx = tid + i * 256;
        int r = idx >> 3, c = idx & 7;
        uint32_t sw = r * 128 + ((c ^ (r & 7)) << 4);
        const uint8_t* g = G + (size_t)(r0 + r) * CDIM + koff + c * 16;
        asm volatile("cp.async.cg.shared.global [%0], [%1], 16;"
                     :: "r"(s + sw), "l"(g));
    }
}

// One phase of 16 double-buffered tiles; fp8 flag selects mma + sources.
template <bool FP8>
__device__ __forceinline__ void gemm_phase(
    uint32_t* sA, uint32_t* sB,
    const void* A0, const void* A1,     // fp8: seg0/seg1 A ptrs; bf16: A0 only
    const void* B0, const void* B1,
    int m0, int n0, int tid, int lane, int wm, int wn,
    float acc[2][8][4])
{
    const int a_r  = wm + (lane & 7) + ((lane >> 3) & 1) * 8;
    const int a_kc = lane >> 4;
    const int b_r  = wn + (lane & 7) + (lane >> 4) * 8;
    const int b_kc = (lane >> 3) & 1;

    // prologue
    if (FP8) {
        stage_f8(sA[0], (const uint8_t*)A0, m0, 0, tid);
        stage_f8(sB[0], (const uint8_t*)B0, n0, 0, tid);
    } else {
        stage_bf(sA[0], (const __nv_bfloat16*)A0, m0, 0, tid);
        stage_bf(sB[0], (const __nv_bfloat16*)B0, n0, 0, tid);
    }
    asm volatile("cp.async.commit_group;" ::: "memory");

    for (int t = 0; t < 16; ++t) {
        const int cur = t & 1, nxt = cur ^ 1;
        if (t + 1 < 16) {
            const int tn = t + 1;
            if (FP8) {
                const uint8_t* An = (tn < 8) ? (const uint8_t*)A0 : (const uint8_t*)A1;
                const uint8_t* Bn = (tn < 8) ? (const uint8_t*)B0 : (const uint8_t*)B1;
                const int ko = (tn & 7) * 128;
                stage_f8(sA[nxt], An, m0, ko, tid);
                stage_f8(sB[nxt], Bn, n0, ko, tid);
            } else {
                const int ko = tn * 64;
                stage_bf(sA[nxt], (const __nv_bfloat16*)A0, m0, ko, tid);
                stage_bf(sB[nxt], (const __nv_bfloat16*)B0, n0, ko, tid);
            }
            asm volatile("cp.async.commit_group;" ::: "memory");
            asm volatile("cp.async.wait_group 1;" ::: "memory");
        } else {
            asm volatile("cp.async.wait_group 0;" ::: "memory");
        }
        __syncthreads();

#pragma unroll
        for (int ks = 0; ks < 4; ++ks) {
            uint32_t af[2][4];
#pragma unroll
            for (int mt = 0; mt < 2; ++mt) {
                const int r = a_r + mt * 16;
                uint32_t addr = sA[cur] + r * 128 + (((ks * 2 + a_kc) ^ (r & 7)) << 4);
                ldsm4(af[mt][0], af[mt][1], af[mt][2], af[mt][3], addr);
            }
            uint32_t bf[8][2];
#pragma unroll
            for (int p = 0; p < 4; ++p) {
                const int r = b_r + p * 16;
                uint32_t addr = sB[cur] + r * 128 + (((ks * 2 + b_kc) ^ (r & 7)) << 4);
                ldsm4(bf[2 * p][0], bf[2 * p][1], bf[2 * p + 1][0], bf[2 * p + 1][1], addr);
            }
#pragma unroll
            for (int mt = 0; mt < 2; ++mt)
#pragma unroll
                for (int nt = 0; nt < 8; ++nt) {
                    if (FP8) mma_fp8(acc[mt][nt], af[mt], bf[nt][0], bf[nt][1]);
                    else     mma_bf16(acc[mt][nt], af[mt], bf[nt][0], bf[nt][1]);
                }
        }
        __syncthreads();
    }
}

// Full split GEMM: cross terms in fp8 (scaled), then hi*hi in bf16.
__device__ __forceinline__ void gemm_core(
    uint32_t* sA, uint32_t* sB,
    const __nv_bfloat16* Ahi, const uint8_t* A8, const uint8_t* A8l,
    const __nv_bfloat16* Bhi, const uint8_t* B8, const uint8_t* B8l,
    int m0, int n0, int tid, int lane, int wm, int wn,
    float acc[2][8][4])
{
    // Phase A: seg0 = A8 x B8l, seg1 = A8l x B8  (each carries one x256 factor)
    gemm_phase<true>(sA, sB, A8, A8l, B8l, B8, m0, n0, tid, lane, wm, wn, acc);
#pragma unroll
    for (int a = 0; a < 2; ++a)
#pragma unroll
        for (int b = 0; b < 8; ++b)
#pragma unroll
            for (int c = 0; c < 4; ++c) acc[a][b][c] *= CROSS_INV;
    // Phase B: bf16 hi*hi
    gemm_phase<false>(sA, sB, Ahi, 0, Bhi, 0, m0, n0, tid, lane, wm, wn, acc);
}

// Fused QKV projection: grid.x = 24 (8 n-blocks x {q,k,v}); writes bf16 hi/lo.
__global__ __launch_bounds__(256) void gemm_qkv(
    const __nv_bfloat16* __restrict__ xhi,
    const uint8_t* __restrict__ x8, const uint8_t* __restrict__ x8l,
    const __nv_bfloat16* __restrict__ wqh,
    const uint8_t* __restrict__ wq8, const uint8_t* __restrict__ wq8l,
    const __nv_bfloat16* __restrict__ wkh,
    const uint8_t* __restrict__ wk8, const uint8_t* __restrict__ wk8l,
    const __nv_bfloat16* __restrict__ wvh,
    const uint8_t* __restrict__ wv8, const uint8_t* __restrict__ wv8l,
    __nv_bfloat16* __restrict__ qh, __nv_bfloat16* __restrict__ ql,
    __nv_bfloat16* __restrict__ kh, __nv_bfloat16* __restrict__ kl,
    __nv_bfloat16* __restrict__ vh, __nv_bfloat16* __restrict__ vl,
    const float* __restrict__ cv, const float* __restrict__ cb)
{
    extern __shared__ char gsm[];
    uint32_t s0 = smem_u32(gsm);
    uint32_t sA[2] = { s0,         s0 + 2 * TILEB };
    uint32_t sB[2] = { s0 + TILEB, s0 + 3 * TILEB };

    const int tid = threadIdx.x, lane = tid & 31, wid = tid >> 5;
    const int wm = (wid >> 1) * 32, wn = (wid & 1) * 64;
    const int wsel = blockIdx.x >> 3;
    const int n0 = (blockIdx.x & 7) * 128;
    const int m0 = blockIdx.y * 128;

    const __nv_bfloat16* Bh = (wsel == 0) ? wqh : (wsel == 1) ? wkh : wvh;
    const uint8_t* B8  = (wsel == 0) ? wq8  : (wsel == 1) ? wk8  : wv8;
    const uint8_t* B8l = (wsel == 0) ? wq8l : (wsel == 1) ? wk8l : wv8l;
    __nv_bfloat16* Oh = (wsel == 0) ? qh : (wsel == 1) ? kh : vh;
    __nv_bfloat16* Ol = (wsel == 0) ? ql : (wsel == 1) ? kl : vl;
    const bool do_cv = (wsel == 0);

    float acc[2][8][4];
#pragma unroll
    for (int a = 0; a < 2; ++a)
#pragma unroll
        for (int b = 0; b < 8; ++b)
#pragma unroll
            for (int c = 0; c < 4; ++c) acc[a][b][c] = 0.0f;

    gemm_core(sA, sB, xhi, x8, x8l, Bh, B8, B8l, m0, n0, tid, lane, wm, wn, acc);

    const int er = lane >> 2, ec = (lane & 3) * 2;
#pragma unroll
    for (int mt = 0; mt < 2; ++mt)
#pragma unroll
        for (int half = 0; half < 2; ++half) {
            const int row = m0 + wm + mt * 16 + er + half * 8;
#pragma unroll
            for (int nt = 0; nt < 8; ++nt) {
                const int col = n0 + wn + nt * 8 + ec;
                float v0 = acc[mt][nt][half * 2 + 0];
                float v1 = acc[mt][nt][half * 2 + 1];
                if (do_cv) {
                    const float* cvr = cv + (size_t)row * CDIM;
                    v0 += cb[col]     * cvr[col];
                    v1 += cb[col + 1] * cvr[col + 1];
                }
                uint32_t hp, lp;
                split2(v0, v1, hp, lp);
                *(uint32_t*)(Oh + (size_t)row * CDIM + col) = hp;
                *(uint32_t*)(Ol + (size_t)row * CDIM + col) = lp;
            }
        }
}

// Output projection: fp32 out + bias
__global__ __launch_bounds__(256) void gemm_out(
    const __nv_bfloat16* __restrict__ Ahi,
    const uint8_t* __restrict__ A8, const uint8_t* __restrict__ A8l,
    const __nv_bfloat16* __restrict__ Bhi,
    const uint8_t* __restrict__ B8, const uint8_t* __restrict__ B8l,
    float* __restrict__ Y, const float* __restrict__ bias)
{
    extern __shared__ char gsm[];
    uint32_t s0 = smem_u32(gsm);
    uint32_t sA[2] = { s0,         s0 + 2 * TILEB };
    uint32_t sB[2] = { s0 + TILEB, s0 + 3 * TILEB };

    const int tid = threadIdx.x, lane = tid & 31, wid = tid >> 5;
    const int wm = (wid >> 1) * 32, wn = (wid & 1) * 64;
    const int m0 = blockIdx.y * 128, n0 = blockIdx.x * 128;

    float acc[2][8][4];
#pragma unroll
    for (int a = 0; a < 2; ++a)
#pragma unroll
        for (int b = 0; b < 8; ++b)
#pragma unroll
            for (int c = 0; c < 4; ++c) acc[a][b][c] = 0.0f;

    gemm_core(sA, sB, Ahi, A8, A8l, Bhi, B8, B8l, m0, n0, tid, lane, wm, wn, acc);

    const int er = lane >> 2, ec = (lane & 3) * 2;
#pragma unroll
    for (int mt = 0; mt < 2; ++mt)
#pragma unroll
        for (int half = 0; half < 2; ++half) {
            const int row = m0 + wm + mt * 16 + er + half * 8;
            float* yrow = Y + (size_t)row * CDIM;
#pragma unroll
            for (int nt = 0; nt < 8; ++nt) {
                const int col = n0 + wn + nt * 8 + ec;
                float2 f;
                f.x = acc[mt][nt][half * 2 + 0] + bias[col];
                f.y = acc[mt][nt][half * 2 + 1] + bias[col + 1];
                *(float2*)(yrow + col) = f;
            }
        }
}

// ---------------------------------------------------------------------------
// Causal flash attention via mma.sync bf16 with hi/lo split (3-term).
// CTA: 128 q-rows of one (b,h); 8 warps, each 16 q-rows x 128 k-cols.
// Heavy q-tiles launch first (qt descending in blockIdx.x).
// ---------------------------------------------------------------------------
__global__ __launch_bounds__(256) void attn_mma(
    const __nv_bfloat16* __restrict__ qhi, const __nv_bfloat16* __restrict__ qlo,
    const __nv_bfloat16* __restrict__ khi, const __nv_bfloat16* __restrict__ klo,
    const __nv_bfloat16* __restrict__ vhi, const __nv_bfloat16* __restrict__ vlo,
    __nv_bfloat16* __restrict__ ohi,
    uint8_t* __restrict__ oh8, uint8_t* __restrict__ ol8)
{
    extern __shared__ char asmem[];
    const uint32_t s0 = smem_u32(asmem);
    const uint32_t sQh = s0,          sQl = s0 + 16384;
    const uint32_t sKh = s0 + 32768,  sKl = s0 + 49152;
    const uint32_t sVh = s0 + 65536,  sVl = s0 + 81920;

    const int tid = threadIdx.x, lane = tid & 31, wid = tid >> 5;
    const int qt = (gridDim.x - 1) - blockIdx.x;   // heavy tiles first
    const int bh = blockIdx.y;
    const int b  = bh >> 4, h = bh & 15;
    const float SCL = 0.125f * 1.4426950408889634f;

    const size_t tokbase = (size_t)b * T_SEQ;
    const size_t headoff = (size_t)h * HD;

    // ---- stage Q (hi+lo)
    {
        const __nv_bfloat16* gh = qhi + (tokbase + qt * 128) * CDIM + headoff;
        const __nv_bfloat16* gl = qlo + (tokbase + qt * 128) * CDIM + headoff;
#pragma unroll
        for (int i = 0; i < 4; ++i) {
            int idx = tid + i * 256;
            int r = idx >> 3, c = idx & 7;
            uint32_t sw = r * 128 + ((c ^ (r & 7)) << 4);
            asm volatile("cp.async.cg.shared.global [%0], [%1], 16;"
                         :: "r"(sQh + sw), "l"(gh + (size_t)r * CDIM + c * 8));
            asm volatile("cp.async.cg.shared.global [%0], [%1], 16;"
                         :: "r"(sQl + sw), "l"(gl + (size_t)r * CDIM + c * 8));
        }
    }
    // ---- stage K/V tile kt=0
    {
        const size_t rb = tokbase * CDIM + headoff;
#pragma unroll
        for (int i = 0; i < 4; ++i) {
            int idx = tid + i * 256;
            int r = idx >> 3, c = idx & 7;
            uint32_t sw = r * 128 + ((c ^ (r & 7)) << 4);
            size_t g = rb + (size_t)r * CDIM + c * 8;
            asm volatile("cp.async.cg.shared.global [%0], [%1], 16;" :: "r"(sKh + sw), "l"(khi + g));
            asm volatile("cp.async.cg.shared.global [%0], [%1], 16;" :: "r"(sKl + sw), "l"(klo + g));
            asm volatile("cp.async.cg.shared.global [%0], [%1], 16;" :: "r"(sVh + sw), "l"(vhi + g));
            asm volatile("cp.async.cg.shared.global [%0], [%1], 16;" :: "r"(sVl + sw), "l"(vlo + g));
        }
    }
    asm volatile("cp.async.commit_group;" ::: "memory");
    asm volatile("cp.async.wait_group 0;" ::: "memory");
    __syncthreads();

    // ---- preload Q fragments
    uint32_t qhf[4][4], qlf[4][4];
    {
        const int a_r  = wid * 16 + (lane & 7) + ((lane >> 3) & 1) * 8;
        const int a_kc = lane >> 4;
#pragma unroll
        for (int ks = 0; ks < 4; ++ks) {
            const int ch = ks * 2 + a_kc;
            uint32_t sw = a_r * 128 + ((ch ^ (a_r & 7)) << 4);
            ldsm4(qhf[ks][0], qhf[ks][1], qhf[ks][2], qhf[ks][3], sQh + sw);
            ldsm4(qlf[ks][0], qlf[ks][1], qlf[ks][2], qlf[ks][3], sQl + sw);
        }
    }

    float o[8][4];
#pragma unroll
    for (int i = 0; i < 8; ++i)
#pragma unroll
        for (int j = 0; j < 4; ++j) o[i][j] = 0.0f;
    float m_[2] = { -1e30f, -1e30f };
    float l_[2] = { 0.0f, 0.0f };

    const int b_rb = (lane & 7) + ((lane >> 4) << 3);
    const int b_kc = (lane >> 3) & 1;
    const int v_rb = (lane & 7) + (((lane >> 3) & 1) << 3);
    const int v_cs = lane >> 4;

    for (int kt = 0; kt <= qt; ++kt) {
        if (kt > 0) {
            const size_t rb = (tokbase + kt * 128) * CDIM + headoff;
#pragma unroll
            for (int i = 0; i < 4; ++i) {
                int idx = tid + i * 256;
                int r = idx >> 3, c = idx & 7;
                uint32_t sw = r * 128 + ((c ^ (r & 7)) << 4);
                size_t g = rb + (size_t)r * CDIM + c * 8;
                asm volatile("cp.async.cg.shared.global [%0], [%1], 16;" :: "r"(sKh + sw), "l"(khi + g));
                asm volatile("cp.async.cg.shared.global [%0], [%1], 16;" :: "r"(sKl + sw), "l"(klo + g));
                asm volatile("cp.async.cg.shared.global [%0], [%1], 16;" :: "r"(sVh + sw), "l"(vhi + g));
                asm volatile("cp.async.cg.shared.global [%0], [%1], 16;" :: "r"(sVl + sw), "l"(vlo + g));
            }
            asm volatile("cp.async.commit_group;" ::: "memory");
            asm volatile("cp.async.wait_group 0;" ::: "memory");
            __syncthreads();
        }

        // ---- S = Q K^T (3-term split)
        float sc[16][4];
#pragma unroll
        for (int t = 0; t < 16; ++t)
#pragma unroll
            for (int j = 0; j < 4; ++j) sc[t][j] = 0.0f;

#pragma unroll
        for (int ks = 0; ks < 4; ++ks) {
#pragma unroll
            for (int g = 0; g < 8; ++g) {
                const int r = g * 16 + b_rb;
                const int ch = ks * 2 + b_kc;
                uint32_t sw = r * 128 + ((ch ^ (r & 7)) << 4);
                uint32_t kh0, kh1, kh2, kh3, kl0, kl1, kl2, kl3;
                ldsm4(kh0, kh1, kh2, kh3, sKh + sw);
                ldsm4(kl0, kl1, kl2, kl3, sKl + sw);
                mma_bf16(sc[2 * g],     qhf[ks], kh0, kh1);
                mma_bf16(sc[2 * g],     qhf[ks], kl0, kl1);
                mma_bf16(sc[2 * g],     qlf[ks], kh0, kh1);
                mma_bf16(sc[2 * g + 1], qhf[ks], kh2, kh3);
                mma_bf16(sc[2 * g + 1], qhf[ks], kl2, kl3);
                mma_bf16(sc[2 * g + 1], qlf[ks], kh2, kh3);
            }
        }

        // ---- scale + causal mask
        const bool diag = (kt == qt);
#pragma unroll
        for (int t = 0; t < 16; ++t)
#pragma unroll
            for (int j = 0; j < 4; ++j) {
                float v = sc[t][j] * SCL;
                if (diag) {
                    const int col = t * 8 + ((lane & 3) << 1) + (j & 1);
                    const int row = (wid << 4) + (lane >> 2) + ((j >> 1) << 3);
                    if (col > row) v = -1e30f;
                }
                sc[t][j] = v;
            }

        // ---- online softmax (log2 domain)
#pragma unroll
        for (int hf = 0; hf < 2; ++hf) {
            float mx = -1e30f;
#pragma unroll
            for (int t = 0; t < 16; ++t)
                mx = fmaxf(mx, fmaxf(sc[t][2 * hf], sc[t][2 * hf + 1]));
            mx = fmaxf(mx, __shfl_xor_sync(0xffffffffu, mx, 1));
            mx = fmaxf(mx, __shfl_xor_sync(0xffffffffu, mx, 2));
            const float mn = fmaxf(m_[hf], mx);
            const float corr = ex2f(m_[hf] - mn);
            float rs = 0.0f;
#pragma unroll
            for (int t = 0; t < 16; ++t) {
                float p0 = ex2f(sc[t][2 * hf]     - mn);
                float p1 = ex2f(sc[t][2 * hf + 1] - mn);
                sc[t][2 * hf] = p0; sc[t][2 * hf + 1] = p1;
                rs += p0 + p1;
            }
            rs += __shfl_xor_sync(0xffffffffu, rs, 1);
            rs += __shfl_xor_sync(0xffffffffu, rs, 2);
            l_[hf] = l_[hf] * corr + rs;
            m_[hf] = mn;
#pragma unroll
            for (int nt = 0; nt < 8; ++nt) {
                o[nt][2 * hf]     *= corr;
                o[nt][2 * hf + 1] *= corr;
            }
        }

        // ---- O += P V (3-term split)
#pragma unroll
        for (int ks2 = 0; ks2 < 8; ++ks2) {
            uint32_t ph[4], pl[4];
            split2(sc[2 * ks2][0],     sc[2 * ks2][1],     ph[0], pl[0]);
            split2(sc[2 * ks2][2],     sc[2 * ks2][3],     ph[1], pl[1]);
            split2(sc[2 * ks2 + 1][0], sc[2 * ks2 + 1][1], ph[2], pl[2]);
            split2(sc[2 * ks2 + 1][2], sc[2 * ks2 + 1][3], ph[3], pl[3]);
#pragma unroll
            for (int ng = 0; ng < 4; ++ng) {
                const int r = ks2 * 16 + v_rb;
                const int ch = ng * 2 + v_cs;
                uint32_t sw = r * 128 + ((ch ^ (r & 7)) << 4);
                uint32_t vh0, vh1, vh2, vh3, vl0, vl1, vl2, vl3;
                ldsm4t(vh0, vh1, vh2, vh3, sVh + sw);
                ldsm4t(vl0, vl1, vl2, vl3, sVl + sw);
                mma_bf16(o[2 * ng],     ph, vh0, vh1);
                mma_bf16(o[2 * ng],     ph, vl0, vl1);
                mma_bf16(o[2 * ng],     pl, vh0, vh1);
                mma_bf16(o[2 * ng + 1], ph, vh2, vh3);
                mma_bf16(o[2 * ng + 1], ph, vl2, vl3);
                mma_bf16(o[2 * ng + 1], pl, vh2, vh3);
            }
        }
        __syncthreads();
    }

    // ---- epilogue: normalize, emit bf16 hi + fp8(x) + fp8(256*lo)
#pragma unroll
    for (int hf = 0; hf < 2; ++hf) {
        const float inv = 1.0f / l_[hf];
        const int row = qt * 128 + wid * 16 + (lane >> 2) + hf * 8;
        __nv_bfloat16* oh = ohi + (tokbase + row) * CDIM + headoff;
        uint8_t* o8  = oh8 + (tokbase + row) * CDIM + headoff;
        uint8_t* o8l = ol8 + (tokbase + row) * CDIM + headoff;
#pragma unroll
        for (int nt = 0; nt < 8; ++nt) {
            const int col = nt * 8 + (lane & 3) * 2;
            float f0 = o[nt][2 * hf]     * inv;
            float f1 = o[nt][2 * hf + 1] * inv;
            uint32_t hp; uint16_t h8, l8;
            split_o8(f0, f1, hp, h8, l8);
            *(uint32_t*)(oh + col) = hp;
            *(uint16_t*)(o8 + col) = h8;
            *(uint16_t*)(o8l + col) = l8;
        }
    }
}

// ---------------------------------------------------------------------------
// Launch.  Inputs: 0:x 1:mask 2:context_vector 3:w_q 4:w_k 5:w_v 6:w_o 7:b_o
//                  8:context_bias    out: f32 [2,2048,1024]
// ---------------------------------------------------------------------------
extern "C" void kernel_launch(void* const* d_in, const int* in_sizes, int n_in,
                              void* d_out, int out_size)
{
    (void)in_sizes; (void)n_in; (void)out_size;
    const float* x  = (const float*)d_in[0];
    const float* cv = (const float*)d_in[2];
    const float* wq = (const float*)d_in[3];
    const float* wk = (const float*)d_in[4];
    const float* wv = (const float*)d_in[5];
    const float* wo = (const float*)d_in[6];
    const float* bo = (const float*)d_in[7];
    const float* cb = (const float*)d_in[8];
    float* out = (float*)d_out;

    __nv_bfloat16 *xhi, *wqh, *wkh, *wvh, *woh;
    __nv_bfloat16 *qh, *ql, *kh, *kl, *vh, *vl, *ah;
    uint8_t *x8, *x8l, *wq8, *wq8l, *wk8, *wk8l, *wv8, *wv8l, *wo8, *wo8l, *a8, *a8l;
    cudaGetSymbolAddress((void**)&xhi, g_xhi);
    cudaGetSymbolAddress((void**)&x8,  g_xhi8); cudaGetSymbolAddress((void**)&x8l, g_xlo8);
    cudaGetSymbolAddress((void**)&wqh, g_wqh);
    cudaGetSymbolAddress((void**)&wq8, g_wq8);  cudaGetSymbolAddress((void**)&wq8l, g_wq8l);
    cudaGetSymbolAddress((void**)&wkh, g_wkh);
    cudaGetSymbolAddress((void**)&wk8, g_wk8);  cudaGetSymbolAddress((void**)&wk8l, g_wk8l);
    cudaGetSymbolAddress((void**)&wvh, g_wvh);
    cudaGetSymbolAddress((void**)&wv8, g_wv8);  cudaGetSymbolAddress((void**)&wv8l, g_wv8l);
    cudaGetSymbolAddress((void**)&woh, g_woh);
    cudaGetSymbolAddress((void**)&wo8, g_wo8);  cudaGetSymbolAddress((void**)&wo8l, g_wo8l);
    cudaGetSymbolAddress((void**)&qh,  g_qhi);  cudaGetSymbolAddress((void**)&ql,  g_qlo);
    cudaGetSymbolAddress((void**)&kh,  g_khi);  cudaGetSymbolAddress((void**)&kl,  g_klo);
    cudaGetSymbolAddress((void**)&vh,  g_vhi);  cudaGetSymbolAddress((void**)&vl,  g_vlo);
    cudaGetSymbolAddress((void**)&ah,  g_ahi);
    cudaGetSymbolAddress((void**)&a8,  g_ah8);  cudaGetSymbolAddress((void**)&a8l, g_al8);

    const int gemm_smem = 4 * TILEB;   // 65536
    cudaFuncSetAttribute(gemm_qkv, cudaFuncAttributeMaxDynamicSharedMemorySize, gemm_smem);
    cudaFuncSetAttribute(gemm_out, cudaFuncAttributeMaxDynamicSharedMemorySize, gemm_smem);
    const int attn_smem = 6 * 16384;   // 98304
    cudaFuncSetAttribute(attn_mma, cudaFuncAttributeMaxDynamicSharedMemorySize, attn_smem);

    const int NX4 = MTOK * CDIM / 4;
    const int NW4 = CDIM * CDIM / 4;

    split3<<<1024, 256>>>(x,  xhi, x8,  x8l,  NX4);
    split3<<<512, 256>>>(wq, wqh, wq8, wq8l, NW4);
    split3<<<512, 256>>>(wk, wkh, wk8, wk8l, NW4);
    split3<<<512, 256>>>(wv, wvh, wv8, wv8l, NW4);
    split3<<<512, 256>>>(wo, woh, wo8, wo8l, NW4);

    gemm_qkv<<<dim3(24, MTOK / 128), 256, gemm_smem>>>(
        xhi, x8, x8l,
        wqh, wq8, wq8l, wkh, wk8, wk8l, wvh, wv8, wv8l,
        qh, ql, kh, kl, vh, vl, cv, cb);

    attn_mma<<<dim3(T_SEQ / 128, NB * NH), 256, attn_smem>>>(
        qh, ql, kh, kl, vh, vl, ah, a8, a8l);

    gemm_out<<<dim3(CDIM / 128, MTOK / 128), 256, gemm_smem>>>(
        ah, a8, a8l, woh, wo8, wo8l, out, bo);
}

// round 6
// speedup vs baseline: 1.1503x; 1.1503x over previous
#include <cuda_runtime.h>
#include <cuda_bf16.h>
#include <math.h>
#include <stdint.h>

#define T_SEQ 2048
#define CDIM  1024
#define NB    2
#define NH    16
#define HD    64
#define MTOK  (NB * T_SEQ)   // 4096 token rows

// ---------------------------------------------------------------------------
// Scratch (static device globals: allocation-free per harness rules)
// ---------------------------------------------------------------------------
__device__ __nv_bfloat16 g_xhi[(size_t)MTOK * CDIM];
__device__ __nv_bfloat16 g_xlo[(size_t)MTOK * CDIM];
__device__ __nv_bfloat16 g_wqh[(size_t)CDIM * CDIM];
__device__ __nv_bfloat16 g_wql[(size_t)CDIM * CDIM];
__device__ __nv_bfloat16 g_wkh[(size_t)CDIM * CDIM];
__device__ __nv_bfloat16 g_wkl[(size_t)CDIM * CDIM];
__device__ __nv_bfloat16 g_wvh[(size_t)CDIM * CDIM];
__device__ __nv_bfloat16 g_wvl[(size_t)CDIM * CDIM];
__device__ __nv_bfloat16 g_woh[(size_t)CDIM * CDIM];
__device__ __nv_bfloat16 g_wol[(size_t)CDIM * CDIM];
__device__ __nv_bfloat16 g_qhi[(size_t)MTOK * CDIM];
__device__ __nv_bfloat16 g_qlo[(size_t)MTOK * CDIM];
__device__ __nv_bfloat16 g_khi[(size_t)MTOK * CDIM];
__device__ __nv_bfloat16 g_klo[(size_t)MTOK * CDIM];
__device__ __nv_bfloat16 g_vhi[(size_t)MTOK * CDIM];
__device__ __nv_bfloat16 g_vlo[(size_t)MTOK * CDIM];
__device__ __nv_bfloat16 g_ahi[(size_t)MTOK * CDIM];
__device__ __nv_bfloat16 g_alo[(size_t)MTOK * CDIM];

// ---------------------------------------------------------------------------
// Helpers
// ---------------------------------------------------------------------------
__device__ __forceinline__ uint32_t smem_u32(const void* p) {
    uint32_t a;
    asm("{ .reg .u64 t; cvta.to.shared.u64 t, %1; cvt.u32.u64 %0, t; }"
        : "=r"(a) : "l"(p));
    return a;
}
__device__ __forceinline__ float ex2f(float x) {
    float y; asm("ex2.approx.ftz.f32 %0, %1;" : "=f"(y) : "f"(x)); return y;
}
__device__ __forceinline__ void ldsm4(uint32_t& r0, uint32_t& r1,
                                      uint32_t& r2, uint32_t& r3, uint32_t addr) {
    asm volatile("ldmatrix.sync.aligned.m8n8.x4.shared.b16 {%0,%1,%2,%3}, [%4];"
                 : "=r"(r0), "=r"(r1), "=r"(r2), "=r"(r3) : "r"(addr));
}
__device__ __forceinline__ void ldsm4t(uint32_t& r0, uint32_t& r1,
                                       uint32_t& r2, uint32_t& r3, uint32_t addr) {
    asm volatile("ldmatrix.sync.aligned.m8n8.x4.trans.shared.b16 {%0,%1,%2,%3}, [%4];"
                 : "=r"(r0), "=r"(r1), "=r"(r2), "=r"(r3) : "r"(addr));
}
__device__ __forceinline__ void mma_bf16(float* c, const uint32_t* a,
                                         uint32_t b0, uint32_t b1) {
    asm volatile(
        "mma.sync.aligned.m16n8k16.row.col.f32.bf16.bf16.f32 "
        "{%0,%1,%2,%3}, {%4,%5,%6,%7}, {%8,%9}, {%0,%1,%2,%3};"
        : "+f"(c[0]), "+f"(c[1]), "+f"(c[2]), "+f"(c[3])
        : "r"(a[0]), "r"(a[1]), "r"(a[2]), "r"(a[3]), "r"(b0), "r"(b1));
}
__device__ __forceinline__ uint32_t packbf(float lo, float hi) {
    uint32_t d;
    asm("cvt.rn.bf16x2.f32 %0, %1, %2;" : "=r"(d) : "f"(hi), "f"(lo));
    return d;
}
__device__ __forceinline__ void split2(float f0, float f1, uint32_t& hp, uint32_t& lp) {
    hp = packbf(f0, f1);
    float h0 = __uint_as_float(hp << 16);
    float h1 = __uint_as_float(hp & 0xffff0000u);
    lp = packbf(f0 - h0, f1 - h1);
}

// ---------------------------------------------------------------------------
// fp32 -> bf16 hi/lo split (vectorized x4)
// ---------------------------------------------------------------------------
__global__ __launch_bounds__(256) void split_bf16(
    const float* __restrict__ in, __nv_bfloat16* __restrict__ hi,
    __nv_bfloat16* __restrict__ lo, int n4)
{
    int i = blockIdx.x * blockDim.x + threadIdx.x;
    const int stride = gridDim.x * blockDim.x;
    for (; i < n4; i += stride) {
        float4 v = *(const float4*)(in + (size_t)i * 4);
        uint32_t h01, l01, h23, l23;
        split2(v.x, v.y, h01, l01);
        split2(v.z, v.w, h23, l23);
        uint2 hh; hh.x = h01; hh.y = h23;
        uint2 ll; ll.x = l01; ll.y = l23;
        *(uint2*)(hi + (size_t)i * 4) = hh;
        *(uint2*)(lo + (size_t)i * 4) = ll;
    }
}

// ---------------------------------------------------------------------------
// GEMM machinery: CTA 128x128, 8 warps (32x64 warp tile), K-tile 64,
// cp.async double buffer, chunk-XOR swizzle, split-bf16 3-term K loop.
// ---------------------------------------------------------------------------
#define GEMM_NT 48          // 3 segments * (1024/64)
#define TILEB   16384       // 128 * 128B

__device__ __forceinline__ void stage_g(
    uint32_t s, const __nv_bfloat16* __restrict__ G, int r0, int koff, int tid)
{
#pragma unroll
    for (int i = 0; i < 4; ++i) {
        int idx = tid + i * 256;
        int r = idx >> 3, c = idx & 7;
        uint32_t sw = r * 128 + ((c ^ (r & 7)) << 4);
        const __nv_bfloat16* g = G + (size_t)(r0 + r) * CDIM + koff + c * 8;
        asm volatile("cp.async.cg.shared.global [%0], [%1], 16;"
                     :: "r"(s + sw), "l"(g));
    }
}

__device__ __forceinline__ void gemm_core(
    uint32_t* sA, uint32_t* sB,
    const __nv_bfloat16* Ahi, const __nv_bfloat16* Alo,
    const __nv_bfloat16* Bhi, const __nv_bfloat16* Blo,
    int m0, int n0, int tid, int lane, int wm, int wn,
    float acc[2][8][4])
{
    const __nv_bfloat16* segA[3] = { Ahi, Ahi, Alo };
    const __nv_bfloat16* segB[3] = { Bhi, Blo, Bhi };

    const int a_r  = wm + (lane & 7) + ((lane >> 3) & 1) * 8;
    const int a_kc = lane >> 4;
    const int b_r  = wn + (lane & 7) + (lane >> 4) * 8;
    const int b_kc = (lane >> 3) & 1;

    stage_g(sA[0], segA[0], m0, 0, tid);
    stage_g(sB[0], segB[0], n0, 0, tid);
    asm volatile("cp.async.commit_group;" ::: "memory");

    for (int t = 0; t < GEMM_NT; ++t) {
        const int cur = t & 1, nxt = cur ^ 1;
        if (t + 1 < GEMM_NT) {
            const int tn = t + 1, sg = tn >> 4, ko = (tn & 15) * 64;
            stage_g(sA[nxt], segA[sg], m0, ko, tid);
            stage_g(sB[nxt], segB[sg], n0, ko, tid);
            asm volatile("cp.async.commit_group;" ::: "memory");
            asm volatile("cp.async.wait_group 1;" ::: "memory");
        } else {
            asm volatile("cp.async.wait_group 0;" ::: "memory");
        }
        __syncthreads();

#pragma unroll
        for (int ks = 0; ks < 4; ++ks) {
            uint32_t af[2][4];
#pragma unroll
            for (int mt = 0; mt < 2; ++mt) {
                const int r = a_r + mt * 16;
                uint32_t addr = sA[cur] + r * 128 + (((ks * 2 + a_kc) ^ (r & 7)) << 4);
                ldsm4(af[mt][0], af[mt][1], af[mt][2], af[mt][3], addr);
            }
            uint32_t bf[8][2];
#pragma unroll
            for (int p = 0; p < 4; ++p) {
                const int r = b_r + p * 16;
                uint32_t addr = sB[cur] + r * 128 + (((ks * 2 + b_kc) ^ (r & 7)) << 4);
                ldsm4(bf[2 * p][0], bf[2 * p][1], bf[2 * p + 1][0], bf[2 * p + 1][1], addr);
            }
#pragma unroll
            for (int mt = 0; mt < 2; ++mt)
#pragma unroll
                for (int nt = 0; nt < 8; ++nt)
                    mma_bf16(acc[mt][nt], af[mt], bf[nt][0], bf[nt][1]);
        }
        __syncthreads();
    }
}

// Fused QKV projection: grid.x = 24 (8 n-blocks x {q,k,v}); writes bf16 hi/lo.
__global__ __launch_bounds__(256) void gemm_qkv(
    const __nv_bfloat16* __restrict__ xhi, const __nv_bfloat16* __restrict__ xlo,
    const __nv_bfloat16* __restrict__ wqh, const __nv_bfloat16* __restrict__ wql,
    const __nv_bfloat16* __restrict__ wkh, const __nv_bfloat16* __restrict__ wkl,
    const __nv_bfloat16* __restrict__ wvh, const __nv_bfloat16* __restrict__ wvl,
    __nv_bfloat16* __restrict__ qh, __nv_bfloat16* __restrict__ ql,
    __nv_bfloat16* __restrict__ kh, __nv_bfloat16* __restrict__ kl,
    __nv_bfloat16* __restrict__ vh, __nv_bfloat16* __restrict__ vl,
    const float* __restrict__ cv, const float* __restrict__ cb)
{
    extern __shared__ char gsm[];
    uint32_t s0 = smem_u32(gsm);
    uint32_t sA[2] = { s0,         s0 + 2 * TILEB };
    uint32_t sB[2] = { s0 + TILEB, s0 + 3 * TILEB };

    const int tid = threadIdx.x, lane = tid & 31, wid = tid >> 5;
    const int wm = (wid >> 1) * 32, wn = (wid & 1) * 64;
    const int wsel = blockIdx.x >> 3;
    const int n0 = (blockIdx.x & 7) * 128;
    const int m0 = blockIdx.y * 128;

    const __nv_bfloat16* Bh = (wsel == 0) ? wqh : (wsel == 1) ? wkh : wvh;
    const __nv_bfloat16* Bl = (wsel == 0) ? wql : (wsel == 1) ? wkl : wvl;
    __nv_bfloat16* Oh = (wsel == 0) ? qh : (wsel == 1) ? kh : vh;
    __nv_bfloat16* Ol = (wsel == 0) ? ql : (wsel == 1) ? kl : vl;
    const bool do_cv = (wsel == 0);

    float acc[2][8][4];
#pragma unroll
    for (int a = 0; a < 2; ++a)
#pragma unroll
        for (int b = 0; b < 8; ++b)
#pragma unroll
            for (int c = 0; c < 4; ++c) acc[a][b][c] = 0.0f;

    gemm_core(sA, sB, xhi, xlo, Bh, Bl, m0, n0, tid, lane, wm, wn, acc);

    const int er = lane >> 2, ec = (lane & 3) * 2;
#pragma unroll
    for (int mt = 0; mt < 2; ++mt)
#pragma unroll
        for (int half = 0; half < 2; ++half) {
            const int row = m0 + wm + mt * 16 + er + half * 8;
#pragma unroll
            for (int nt = 0; nt < 8; ++nt) {
                const int col = n0 + wn + nt * 8 + ec;
                float v0 = acc[mt][nt][half * 2 + 0];
                float v1 = acc[mt][nt][half * 2 + 1];
                if (do_cv) {
                    const float* cvr = cv + (size_t)row * CDIM;
                    v0 += cb[col]     * cvr[col];
                    v1 += cb[col + 1] * cvr[col + 1];
                }
                uint32_t hp, lp;
                split2(v0, v1, hp, lp);
                *(uint32_t*)(Oh + (size_t)row * CDIM + col) = hp;
                *(uint32_t*)(Ol + (size_t)row * CDIM + col) = lp;
            }
        }
}

// Output projection: fp32 out + bias
__global__ __launch_bounds__(256) void gemm_out(
    const __nv_bfloat16* __restrict__ Ahi, const __nv_bfloat16* __restrict__ Alo,
    const __nv_bfloat16* __restrict__ Bhi, const __nv_bfloat16* __restrict__ Blo,
    float* __restrict__ Y, const float* __restrict__ bias)
{
    extern __shared__ char gsm[];
    uint32_t s0 = smem_u32(gsm);
    uint32_t sA[2] = { s0,         s0 + 2 * TILEB };
    uint32_t sB[2] = { s0 + TILEB, s0 + 3 * TILEB };

    const int tid = threadIdx.x, lane = tid & 31, wid = tid >> 5;
    const int wm = (wid >> 1) * 32, wn = (wid & 1) * 64;
    const int m0 = blockIdx.y * 128, n0 = blockIdx.x * 128;

    float acc[2][8][4];
#pragma unroll
    for (int a = 0; a < 2; ++a)
#pragma unroll
        for (int b = 0; b < 8; ++b)
#pragma unroll
            for (int c = 0; c < 4; ++c) acc[a][b][c] = 0.0f;

    gemm_core(sA, sB, Ahi, Alo, Bhi, Blo, m0, n0, tid, lane, wm, wn, acc);

    const int er = lane >> 2, ec = (lane & 3) * 2;
#pragma unroll
    for (int mt = 0; mt < 2; ++mt)
#pragma unroll
        for (int half = 0; half < 2; ++half) {
            const int row = m0 + wm + mt * 16 + er + half * 8;
            float* yrow = Y + (size_t)row * CDIM;
#pragma unroll
            for (int nt = 0; nt < 8; ++nt) {
                const int col = n0 + wn + nt * 8 + ec;
                float2 f;
                f.x = acc[mt][nt][half * 2 + 0] + bias[col];
                f.y = acc[mt][nt][half * 2 + 1] + bias[col + 1];
                *(float2*)(yrow + col) = f;
            }
        }
}

// ---------------------------------------------------------------------------
// Causal flash attention via mma.sync bf16, hi/lo split (3-term).
// CTA: 128 q-rows of one (b,h); 8 warps, each 16 q-rows x 128 k-cols.
// K/V double-buffered in smem; prefetch of kt+1 overlaps compute of kt.
// Heavy q-tiles launch first.
// ---------------------------------------------------------------------------
__device__ __forceinline__ void stage_kv(
    uint32_t kvb,
    const __nv_bfloat16* __restrict__ khi, const __nv_bfloat16* __restrict__ klo,
    const __nv_bfloat16* __restrict__ vhi, const __nv_bfloat16* __restrict__ vlo,
    size_t rb, int tid)
{
#pragma unroll
    for (int i = 0; i < 4; ++i) {
        int idx = tid + i * 256;
        int r = idx >> 3, c = idx & 7;
        uint32_t sw = r * 128 + ((c ^ (r & 7)) << 4);
        size_t g = rb + (size_t)r * CDIM + c * 8;
        asm volatile("cp.async.cg.shared.global [%0], [%1], 16;" :: "r"(kvb + sw),         "l"(khi + g));
        asm volatile("cp.async.cg.shared.global [%0], [%1], 16;" :: "r"(kvb + 16384 + sw), "l"(klo + g));
        asm volatile("cp.async.cg.shared.global [%0], [%1], 16;" :: "r"(kvb + 32768 + sw), "l"(vhi + g));
        asm volatile("cp.async.cg.shared.global [%0], [%1], 16;" :: "r"(kvb + 49152 + sw), "l"(vlo + g));
    }
    asm volatile("cp.async.commit_group;" ::: "memory");
}

__global__ __launch_bounds__(256) void attn_mma(
    const __nv_bfloat16* __restrict__ qhi, const __nv_bfloat16* __restrict__ qlo,
    const __nv_bfloat16* __restrict__ khi, const __nv_bfloat16* __restrict__ klo,
    const __nv_bfloat16* __restrict__ vhi, const __nv_bfloat16* __restrict__ vlo,
    __nv_bfloat16* __restrict__ ohi, __nv_bfloat16* __restrict__ olo)
{
    extern __shared__ char asmem[];
    const uint32_t s0 = smem_u32(asmem);
    const uint32_t sQh = s0, sQl = s0 + 16384;
    const uint32_t kv0 = s0 + 32768;          // 2 buffers x 64KB: Kh,Kl,Vh,Vl

    const int tid = threadIdx.x, lane = tid & 31, wid = tid >> 5;
    const int qt = (gridDim.x - 1) - blockIdx.x;   // heavy tiles first
    const int bh = blockIdx.y;
    const int b  = bh >> 4, h = bh & 15;
    const float SCL = 0.125f * 1.4426950408889634f;

    const size_t tokbase = (size_t)b * T_SEQ;
    const size_t headoff = (size_t)h * HD;

    // ---- stage Q (hi+lo) + K/V tile 0 under one commit group
    {
        const __nv_bfloat16* gh = qhi + (tokbase + qt * 128) * CDIM + headoff;
        const __nv_bfloat16* gl = qlo + (tokbase + qt * 128) * CDIM + headoff;
#pragma unroll
        for (int i = 0; i < 4; ++i) {
            int idx = tid + i * 256;
            int r = idx >> 3, c = idx & 7;
            uint32_t sw = r * 128 + ((c ^ (r & 7)) << 4);
            asm volatile("cp.async.cg.shared.global [%0], [%1], 16;"
                         :: "r"(sQh + sw), "l"(gh + (size_t)r * CDIM + c * 8));
            asm volatile("cp.async.cg.shared.global [%0], [%1], 16;"
                         :: "r"(sQl + sw), "l"(gl + (size_t)r * CDIM + c * 8));
        }
    }
    stage_kv(kv0, khi, klo, vhi, vlo, tokbase * CDIM + headoff, tid);

    uint32_t qhf[4][4], qlf[4][4];
    float o[8][4];
#pragma unroll
    for (int i = 0; i < 8; ++i)
#pragma unroll
        for (int j = 0; j < 4; ++j) o[i][j] = 0.0f;
    float m_[2] = { -1e30f, -1e30f };
    float l_[2] = { 0.0f, 0.0f };

    const int b_rb = (lane & 7) + ((lane >> 4) << 3);
    const int b_kc = (lane >> 3) & 1;
    const int v_rb = (lane & 7) + (((lane >> 3) & 1) << 3);
    const int v_cs = lane >> 4;

    for (int kt = 0; kt <= qt; ++kt) {
        const int cur = kt & 1;
        const uint32_t kvb = kv0 + cur * 65536;
        if (kt < qt) {
            // prefetch kt+1 into the other buffer; overlaps compute below
            stage_kv(kv0 + (cur ^ 1) * 65536, khi, klo, vhi, vlo,
                     (tokbase + (size_t)(kt + 1) * 128) * CDIM + headoff, tid);
            asm volatile("cp.async.wait_group 1;" ::: "memory");
        } else {
            asm volatile("cp.async.wait_group 0;" ::: "memory");
        }
        __syncthreads();

        if (kt == 0) {   // Q fragments (now resident)
            const int a_r  = wid * 16 + (lane & 7) + ((lane >> 3) & 1) * 8;
            const int a_kc = lane >> 4;
#pragma unroll
            for (int ks = 0; ks < 4; ++ks) {
                const int ch = ks * 2 + a_kc;
                uint32_t sw = a_r * 128 + ((ch ^ (a_r & 7)) << 4);
                ldsm4(qhf[ks][0], qhf[ks][1], qhf[ks][2], qhf[ks][3], sQh + sw);
                ldsm4(qlf[ks][0], qlf[ks][1], qlf[ks][2], qlf[ks][3], sQl + sw);
            }
        }

        const uint32_t sKh = kvb, sKl = kvb + 16384;
        const uint32_t sVh = kvb + 32768, sVl = kvb + 49152;

        // ---- S = Q K^T (3-term split)
        float sc[16][4];
#pragma unroll
        for (int t = 0; t < 16; ++t)
#pragma unroll
            for (int j = 0; j < 4; ++j) sc[t][j] = 0.0f;

#pragma unroll
        for (int ks = 0; ks < 4; ++ks) {
#pragma unroll
            for (int g = 0; g < 8; ++g) {
                const int r = g * 16 + b_rb;
                const int ch = ks * 2 + b_kc;
                uint32_t sw = r * 128 + ((ch ^ (r & 7)) << 4);
                uint32_t kh0, kh1, kh2, kh3, kl0, kl1, kl2, kl3;
                ldsm4(kh0, kh1, kh2, kh3, sKh + sw);
                ldsm4(kl0, kl1, kl2, kl3, sKl + sw);
                mma_bf16(sc[2 * g],     qhf[ks], kh0, kh1);
                mma_bf16(sc[2 * g],     qhf[ks], kl0, kl1);
                mma_bf16(sc[2 * g],     qlf[ks], kh0, kh1);
                mma_bf16(sc[2 * g + 1], qhf[ks], kh2, kh3);
                mma_bf16(sc[2 * g + 1], qhf[ks], kl2, kl3);
                mma_bf16(sc[2 * g + 1], qlf[ks], kh2, kh3);
            }
        }

        // ---- scale + causal mask (diagonal tile only)
        const bool diag = (kt == qt);
#pragma unroll
        for (int t = 0; t < 16; ++t)
#pragma unroll
            for (int j = 0; j < 4; ++j) {
                float v = sc[t][j] * SCL;
                if (diag) {
                    const int col = t * 8 + ((lane & 3) << 1) + (j & 1);
                    const int row = (wid << 4) + (lane >> 2) + ((j >> 1) << 3);
                    if (col > row) v = -1e30f;
                }
                sc[t][j] = v;
            }

        // ---- online softmax (log2 domain)
#pragma unroll
        for (int hf = 0; hf < 2; ++hf) {
            float mx = -1e30f;
#pragma unroll
            for (int t = 0; t < 16; ++t)
                mx = fmaxf(mx, fmaxf(sc[t][2 * hf], sc[t][2 * hf + 1]));
            mx = fmaxf(mx, __shfl_xor_sync(0xffffffffu, mx, 1));
            mx = fmaxf(mx, __shfl_xor_sync(0xffffffffu, mx, 2));
            const float mn = fmaxf(m_[hf], mx);
            const float corr = ex2f(m_[hf] - mn);
            float rs = 0.0f;
#pragma unroll
            for (int t = 0; t < 16; ++t) {
                float p0 = ex2f(sc[t][2 * hf]     - mn);
                float p1 = ex2f(sc[t][2 * hf + 1] - mn);
                sc[t][2 * hf] = p0; sc[t][2 * hf + 1] = p1;
                rs += p0 + p1;
            }
            rs += __shfl_xor_sync(0xffffffffu, rs, 1);
            rs += __shfl_xor_sync(0xffffffffu, rs, 2);
            l_[hf] = l_[hf] * corr + rs;
            m_[hf] = mn;
#pragma unroll
            for (int nt = 0; nt < 8; ++nt) {
                o[nt][2 * hf]     *= corr;
                o[nt][2 * hf + 1] *= corr;
            }
        }

        // ---- O += P V (3-term split); P fragments built in registers
#pragma unroll
        for (int ks2 = 0; ks2 < 8; ++ks2) {
            uint32_t ph[4], pl[4];
            split2(sc[2 * ks2][0],     sc[2 * ks2][1],     ph[0], pl[0]);
            split2(sc[2 * ks2][2],     sc[2 * ks2][3],     ph[1], pl[1]);
            split2(sc[2 * ks2 + 1][0], sc[2 * ks2 + 1][1], ph[2], pl[2]);
            split2(sc[2 * ks2 + 1][2], sc[2 * ks2 + 1][3], ph[3], pl[3]);
#pragma unroll
            for (int ng = 0; ng < 4; ++ng) {
                const int r = ks2 * 16 + v_rb;
                const int ch = ng * 2 + v_cs;
                uint32_t sw = r * 128 + ((ch ^ (r & 7)) << 4);
                uint32_t vh0, vh1, vh2, vh3, vl0, vl1, vl2, vl3;
                ldsm4t(vh0, vh1, vh2, vh3, sVh + sw);
                ldsm4t(vl0, vl1, vl2, vl3, sVl + sw);
                mma_bf16(o[2 * ng],     ph, vh0, vh1);
                mma_bf16(o[2 * ng],     ph, vl0, vl1);
                mma_bf16(o[2 * ng],     pl, vh0, vh1);
                mma_bf16(o[2 * ng + 1], ph, vh2, vh3);
                mma_bf16(o[2 * ng + 1], ph, vl2, vl3);
                mma_bf16(o[2 * ng + 1], pl, vh2, vh3);
            }
        }
        __syncthreads();   // done reading buffer cur before iter kt+2 restages it
    }

    // ---- epilogue: normalize, split hi/lo, store
#pragma unroll
    for (int hf = 0; hf < 2; ++hf) {
        const float inv = 1.0f / l_[hf];
        const int row = qt * 128 + wid * 16 + (lane >> 2) + hf * 8;
        __nv_bfloat16* oh = ohi + (tokbase + row) * CDIM + headoff;
        __nv_bfloat16* ol = olo + (tokbase + row) * CDIM + headoff;
#pragma unroll
        for (int nt = 0; nt < 8; ++nt) {
            const int col = nt * 8 + (lane & 3) * 2;
            float f0 = o[nt][2 * hf]     * inv;
            float f1 = o[nt][2 * hf + 1] * inv;
            uint32_t hp, lp;
            split2(f0, f1, hp, lp);
            *(uint32_t*)(oh + col) = hp;
            *(uint32_t*)(ol + col) = lp;
        }
    }
}

// ---------------------------------------------------------------------------
// Launch.  Inputs: 0:x 1:mask 2:context_vector 3:w_q 4:w_k 5:w_v 6:w_o 7:b_o
//                  8:context_bias    out: f32 [2,2048,1024]
// ---------------------------------------------------------------------------
extern "C" void kernel_launch(void* const* d_in, const int* in_sizes, int n_in,
                              void* d_out, int out_size)
{
    (void)in_sizes; (void)n_in; (void)out_size;
    const float* x  = (const float*)d_in[0];
    const float* cv = (const float*)d_in[2];
    const float* wq = (const float*)d_in[3];
    const float* wk = (const float*)d_in[4];
    const float* wv = (const float*)d_in[5];
    const float* wo = (const float*)d_in[6];
    const float* bo = (const float*)d_in[7];
    const float* cb = (const float*)d_in[8];
    float* out = (float*)d_out;

    __nv_bfloat16 *xhi, *xlo, *wqh, *wql, *wkh, *wkl, *wvh, *wvl, *woh, *wol;
    __nv_bfloat16 *qh, *ql, *kh, *kl, *vh, *vl, *ah, *al;
    cudaGetSymbolAddress((void**)&xhi, g_xhi); cudaGetSymbolAddress((void**)&xlo, g_xlo);
    cudaGetSymbolAddress((void**)&wqh, g_wqh); cudaGetSymbolAddress((void**)&wql, g_wql);
    cudaGetSymbolAddress((void**)&wkh, g_wkh); cudaGetSymbolAddress((void**)&wkl, g_wkl);
    cudaGetSymbolAddress((void**)&wvh, g_wvh); cudaGetSymbolAddress((void**)&wvl, g_wvl);
    cudaGetSymbolAddress((void**)&woh, g_woh); cudaGetSymbolAddress((void**)&wol, g_wol);
    cudaGetSymbolAddress((void**)&qh,  g_qhi); cudaGetSymbolAddress((void**)&ql,  g_qlo);
    cudaGetSymbolAddress((void**)&kh,  g_khi); cudaGetSymbolAddress((void**)&kl,  g_klo);
    cudaGetSymbolAddress((void**)&vh,  g_vhi); cudaGetSymbolAddress((void**)&vl,  g_vlo);
    cudaGetSymbolAddress((void**)&ah,  g_ahi); cudaGetSymbolAddress((void**)&al,  g_alo);

    const int gemm_smem = 4 * TILEB;   // 65536
    cudaFuncSetAttribute(gemm_qkv, cudaFuncAttributeMaxDynamicSharedMemorySize, gemm_smem);
    cudaFuncSetAttribute(gemm_out, cudaFuncAttributeMaxDynamicSharedMemorySize, gemm_smem);
    const int attn_smem = 2 * 16384 + 2 * 65536;   // Q hi/lo + 2 KV buffers = 163840
    cudaFuncSetAttribute(attn_mma, cudaFuncAttributeMaxDynamicSharedMemorySize, attn_smem);

    const int NX4 = MTOK * CDIM / 4;
    const int NW4 = CDIM * CDIM / 4;

    split_bf16<<<1024, 256>>>(x,  xhi, xlo, NX4);
    split_bf16<<<512, 256>>>(wq, wqh, wql, NW4);
    split_bf16<<<512, 256>>>(wk, wkh, wkl, NW4);
    split_bf16<<<512, 256>>>(wv, wvh, wvl, NW4);
    split_bf16<<<512, 256>>>(wo, woh, wol, NW4);

    gemm_qkv<<<dim3(24, MTOK / 128), 256, gemm_smem>>>(
        xhi, xlo, wqh, wql, wkh, wkl, wvh, wvl,
        qh, ql, kh, kl, vh, vl, cv, cb);

    attn_mma<<<dim3(T_SEQ / 128, NB * NH), 256, attn_smem>>>(
        qh, ql, kh, kl, vh, vl, ah, al);

    gemm_out<<<dim3(CDIM / 128, MTOK / 128), 256, gemm_smem>>>(
        ah, al, woh, wol, out, bo);
}

// round 7
// speedup vs baseline: 1.5435x; 1.3419x over previous
#include <cuda_runtime.h>
#include <cuda_fp16.h>
#include <math.h>
#include <stdint.h>

#define T_SEQ 2048
#define CDIM  1024
#define NB    2
#define NH    16
#define HD    64
#define MTOK  (NB * T_SEQ)   // 4096 token rows

// ---------------------------------------------------------------------------
// Scratch (static device globals)
// ---------------------------------------------------------------------------
__device__ __half g_xhi[(size_t)MTOK * CDIM];
__device__ __half g_xlo[(size_t)MTOK * CDIM];
__device__ __half g_wq16[(size_t)CDIM * CDIM];
__device__ __half g_wk16[(size_t)CDIM * CDIM];
__device__ __half g_wv16[(size_t)CDIM * CDIM];
__device__ __half g_wo16[(size_t)CDIM * CDIM];
__device__ __half g_qhi[(size_t)MTOK * CDIM];
__device__ __half g_qlo[(size_t)MTOK * CDIM];
__device__ __half g_k16[(size_t)MTOK * CDIM];
__device__ __half g_v16[(size_t)MTOK * CDIM];
__device__ __half g_ahi[(size_t)MTOK * CDIM];
__device__ __half g_alo[(size_t)MTOK * CDIM];

// ---------------------------------------------------------------------------
// Helpers
// ---------------------------------------------------------------------------
__device__ __forceinline__ uint32_t smem_u32(const void* p) {
    uint32_t a;
    asm("{ .reg .u64 t; cvta.to.shared.u64 t, %1; cvt.u32.u64 %0, t; }"
        : "=r"(a) : "l"(p));
    return a;
}
__device__ __forceinline__ float ex2f(float x) {
    float y; asm("ex2.approx.ftz.f32 %0, %1;" : "=f"(y) : "f"(x)); return y;
}
__device__ __forceinline__ void ldsm4(uint32_t& r0, uint32_t& r1,
                                      uint32_t& r2, uint32_t& r3, uint32_t addr) {
    asm volatile("ldmatrix.sync.aligned.m8n8.x4.shared.b16 {%0,%1,%2,%3}, [%4];"
                 : "=r"(r0), "=r"(r1), "=r"(r2), "=r"(r3) : "r"(addr));
}
__device__ __forceinline__ void ldsm4t(uint32_t& r0, uint32_t& r1,
                                       uint32_t& r2, uint32_t& r3, uint32_t addr) {
    asm volatile("ldmatrix.sync.aligned.m8n8.x4.trans.shared.b16 {%0,%1,%2,%3}, [%4];"
                 : "=r"(r0), "=r"(r1), "=r"(r2), "=r"(r3) : "r"(addr));
}
__device__ __forceinline__ void mma_f16(float* c, const uint32_t* a,
                                        uint32_t b0, uint32_t b1) {
    asm volatile(
        "mma.sync.aligned.m16n8k16.row.col.f32.f16.f16.f32 "
        "{%0,%1,%2,%3}, {%4,%5,%6,%7}, {%8,%9}, {%0,%1,%2,%3};"
        : "+f"(c[0]), "+f"(c[1]), "+f"(c[2]), "+f"(c[3])
        : "r"(a[0]), "r"(a[1]), "r"(a[2]), "r"(a[3]), "r"(b0), "r"(b1));
}
__device__ __forceinline__ uint32_t packh(float f0, float f1) {
    __half2 h = __floats2half2_rn(f0, f1);
    return *(uint32_t*)&h;
}
// split f0,f1 into fp16 hi + fp16 residual pairs
__device__ __forceinline__ void split2h(float f0, float f1, uint32_t& hp, uint32_t& lp) {
    hp = packh(f0, f1);
    __half2 h = *(__half2*)&hp;
    lp = packh(f0 - __low2float(h), f1 - __high2float(h));
}

// ---------------------------------------------------------------------------
// fp32 -> fp16 hi + residual (x4);  and plain fp32 -> fp16 convert (weights)
// ---------------------------------------------------------------------------
__global__ __launch_bounds__(256) void split_f16(
    const float* __restrict__ in, __half* __restrict__ hi,
    __half* __restrict__ lo, int n4)
{
    int i = blockIdx.x * blockDim.x + threadIdx.x;
    const int stride = gridDim.x * blockDim.x;
    for (; i < n4; i += stride) {
        float4 v = *(const float4*)(in + (size_t)i * 4);
        uint32_t h01, l01, h23, l23;
        split2h(v.x, v.y, h01, l01);
        split2h(v.z, v.w, h23, l23);
        uint2 hh; hh.x = h01; hh.y = h23;
        uint2 ll; ll.x = l01; ll.y = l23;
        *(uint2*)(hi + (size_t)i * 4) = hh;
        *(uint2*)(lo + (size_t)i * 4) = ll;
    }
}
__global__ __launch_bounds__(256) void cvt_f16(
    const float* __restrict__ in, __half* __restrict__ out, int n4)
{
    int i = blockIdx.x * blockDim.x + threadIdx.x;
    const int stride = gridDim.x * blockDim.x;
    for (; i < n4; i += stride) {
        float4 v = *(const float4*)(in + (size_t)i * 4);
        uint2 hh; hh.x = packh(v.x, v.y); hh.y = packh(v.z, v.w);
        *(uint2*)(out + (size_t)i * 4) = hh;
    }
}

// ---------------------------------------------------------------------------
// GEMM: Y = (Ah+Al) @ B16^T.  CTA 128x128, 8 warps (32x64), K-tile 64.
// Per k-step stage 3 tiles {Ah, Al, B}; B shared by both A segments.
// 16 double-buffered passes, chunk-XOR swizzle.
// ---------------------------------------------------------------------------
#define NT16  16
#define TILEB 16384       // 128 rows * 128B

__device__ __forceinline__ void stage_g(
    uint32_t s, const __half* __restrict__ G, int r0, int koff, int tid)
{
#pragma unroll
    for (int i = 0; i < 4; ++i) {
        int idx = tid + i * 256;
        int r = idx >> 3, c = idx & 7;
        uint32_t sw = r * 128 + ((c ^ (r & 7)) << 4);
        const __half* g = G + (size_t)(r0 + r) * CDIM + koff + c * 8;
        asm volatile("cp.async.cg.shared.global [%0], [%1], 16;"
                     :: "r"(s + sw), "l"(g));
    }
}

__device__ __forceinline__ void gemm_core(
    uint32_t s0,
    const __half* Ah, const __half* Al, const __half* B16,
    int m0, int n0, int tid, int lane, int wm, int wn,
    float acc[2][8][4])
{
    // buffers: [Ah0, Al0, B0, Ah1, Al1, B1]
    uint32_t sAh[2] = { s0,             s0 + 3 * TILEB };
    uint32_t sAl[2] = { s0 + TILEB,     s0 + 4 * TILEB };
    uint32_t sB [2] = { s0 + 2 * TILEB, s0 + 5 * TILEB };

    const int a_r  = wm + (lane & 7) + ((lane >> 3) & 1) * 8;
    const int a_kc = lane >> 4;
    const int b_r  = wn + (lane & 7) + (lane >> 4) * 8;
    const int b_kc = (lane >> 3) & 1;

    stage_g(sAh[0], Ah, m0, 0, tid);
    stage_g(sAl[0], Al, m0, 0, tid);
    stage_g(sB[0],  B16, n0, 0, tid);
    asm volatile("cp.async.commit_group;" ::: "memory");

    for (int t = 0; t < NT16; ++t) {
        const int cur = t & 1, nxt = cur ^ 1;
        if (t + 1 < NT16) {
            const int ko = (t + 1) * 64;
            stage_g(sAh[nxt], Ah, m0, ko, tid);
            stage_g(sAl[nxt], Al, m0, ko, tid);
            stage_g(sB[nxt],  B16, n0, ko, tid);
            asm volatile("cp.async.commit_group;" ::: "memory");
            asm volatile("cp.async.wait_group 1;" ::: "memory");
        } else {
            asm volatile("cp.async.wait_group 0;" ::: "memory");
        }
        __syncthreads();

#pragma unroll
        for (int ks = 0; ks < 4; ++ks) {
            uint32_t ah[2][4], al[2][4];
#pragma unroll
            for (int mt = 0; mt < 2; ++mt) {
                const int r = a_r + mt * 16;
                uint32_t off = r * 128 + (((ks * 2 + a_kc) ^ (r & 7)) << 4);
                ldsm4(ah[mt][0], ah[mt][1], ah[mt][2], ah[mt][3], sAh[cur] + off);
                ldsm4(al[mt][0], al[mt][1], al[mt][2], al[mt][3], sAl[cur] + off);
            }
            uint32_t bf[8][2];
#pragma unroll
            for (int p = 0; p < 4; ++p) {
                const int r = b_r + p * 16;
                uint32_t off = r * 128 + (((ks * 2 + b_kc) ^ (r & 7)) << 4);
                ldsm4(bf[2 * p][0], bf[2 * p][1], bf[2 * p + 1][0], bf[2 * p + 1][1],
                      sB[cur] + off);
            }
#pragma unroll
            for (int mt = 0; mt < 2; ++mt)
#pragma unroll
                for (int nt = 0; nt < 8; ++nt) {
                    mma_f16(acc[mt][nt], ah[mt], bf[nt][0], bf[nt][1]);
                    mma_f16(acc[mt][nt], al[mt], bf[nt][0], bf[nt][1]);
                }
        }
        __syncthreads();
    }
}

// Fused QKV projection: grid.x = 24 (8 n-blocks x {q,k,v}).
// Q -> fp16 hi/lo split; K,V -> single fp16.
__global__ __launch_bounds__(256) void gemm_qkv(
    const __half* __restrict__ xh, const __half* __restrict__ xl,
    const __half* __restrict__ wq16, const __half* __restrict__ wk16,
    const __half* __restrict__ wv16,
    __half* __restrict__ qh, __half* __restrict__ ql,
    __half* __restrict__ k16, __half* __restrict__ v16,
    const float* __restrict__ cv, const float* __restrict__ cb)
{
    extern __shared__ char gsm[];
    uint32_t s0 = smem_u32(gsm);

    const int tid = threadIdx.x, lane = tid & 31, wid = tid >> 5;
    const int wm = (wid >> 1) * 32, wn = (wid & 1) * 64;
    const int wsel = blockIdx.x >> 3;
    const int n0 = (blockIdx.x & 7) * 128;
    const int m0 = blockIdx.y * 128;

    const __half* B16 = (wsel == 0) ? wq16 : (wsel == 1) ? wk16 : wv16;

    float acc[2][8][4];
#pragma unroll
    for (int a = 0; a < 2; ++a)
#pragma unroll
        for (int b = 0; b < 8; ++b)
#pragma unroll
            for (int c = 0; c < 4; ++c) acc[a][b][c] = 0.0f;

    gemm_core(s0, xh, xl, B16, m0, n0, tid, lane, wm, wn, acc);

    const int er = lane >> 2, ec = (lane & 3) * 2;
#pragma unroll
    for (int mt = 0; mt < 2; ++mt)
#pragma unroll
        for (int half = 0; half < 2; ++half) {
            const int row = m0 + wm + mt * 16 + er + half * 8;
#pragma unroll
            for (int nt = 0; nt < 8; ++nt) {
                const int col = n0 + wn + nt * 8 + ec;
                float v0 = acc[mt][nt][half * 2 + 0];
                float v1 = acc[mt][nt][half * 2 + 1];
                if (wsel == 0) {
                    const float* cvr = cv + (size_t)row * CDIM;
                    v0 += cb[col]     * cvr[col];
                    v1 += cb[col + 1] * cvr[col + 1];
                    uint32_t hp, lp;
                    split2h(v0, v1, hp, lp);
                    *(uint32_t*)(qh + (size_t)row * CDIM + col) = hp;
                    *(uint32_t*)(ql + (size_t)row * CDIM + col) = lp;
                } else {
                    __half* O = (wsel == 1) ? k16 : v16;
                    *(uint32_t*)(O + (size_t)row * CDIM + col) = packh(v0, v1);
                }
            }
        }
}

// Output projection: fp32 out + bias
__global__ __launch_bounds__(256) void gemm_out(
    const __half* __restrict__ ah, const __half* __restrict__ al,
    const __half* __restrict__ wo16,
    float* __restrict__ Y, const float* __restrict__ bias)
{
    extern __shared__ char gsm[];
    uint32_t s0 = smem_u32(gsm);

    const int tid = threadIdx.x, lane = tid & 31, wid = tid >> 5;
    const int wm = (wid >> 1) * 32, wn = (wid & 1) * 64;
    const int m0 = blockIdx.y * 128, n0 = blockIdx.x * 128;

    float acc[2][8][4];
#pragma unroll
    for (int a = 0; a < 2; ++a)
#pragma unroll
        for (int b = 0; b < 8; ++b)
#pragma unroll
            for (int c = 0; c < 4; ++c) acc[a][b][c] = 0.0f;

    gemm_core(s0, ah, al, wo16, m0, n0, tid, lane, wm, wn, acc);

    const int er = lane >> 2, ec = (lane & 3) * 2;
#pragma unroll
    for (int mt = 0; mt < 2; ++mt)
#pragma unroll
        for (int half = 0; half < 2; ++half) {
            const int row = m0 + wm + mt * 16 + er + half * 8;
            float* yrow = Y + (size_t)row * CDIM;
#pragma unroll
            for (int nt = 0; nt < 8; ++nt) {
                const int col = n0 + wn + nt * 8 + ec;
                float2 f;
                f.x = acc[mt][nt][half * 2 + 0] + bias[col];
                f.y = acc[mt][nt][half * 2 + 1] + bias[col + 1];
                *(float2*)(yrow + col) = f;
            }
        }
}

// ---------------------------------------------------------------------------
// Causal flash attention, fp16 mma. Q split 2-term, K/V single fp16,
// P split in registers. CTA: 128 q-rows; 8 warps of 16 q-rows x 128 k-cols.
// K/V double-buffered (32KB/buffer); heavy q-tiles first.
// ---------------------------------------------------------------------------
__device__ __forceinline__ void stage_kv(
    uint32_t kvb, const __half* __restrict__ k16, const __half* __restrict__ v16,
    size_t rb, int tid)
{
#pragma unroll
    for (int i = 0; i < 4; ++i) {
        int idx = tid + i * 256;
        int r = idx >> 3, c = idx & 7;
        uint32_t sw = r * 128 + ((c ^ (r & 7)) << 4);
        size_t g = rb + (size_t)r * CDIM + c * 8;
        asm volatile("cp.async.cg.shared.global [%0], [%1], 16;" :: "r"(kvb + sw),         "l"(k16 + g));
        asm volatile("cp.async.cg.shared.global [%0], [%1], 16;" :: "r"(kvb + 16384 + sw), "l"(v16 + g));
    }
    asm volatile("cp.async.commit_group;" ::: "memory");
}

__global__ __launch_bounds__(256) void attn_mma(
    const __half* __restrict__ qhi, const __half* __restrict__ qlo,
    const __half* __restrict__ k16, const __half* __restrict__ v16,
    __half* __restrict__ ohi, __half* __restrict__ olo)
{
    extern __shared__ char asmem[];
    const uint32_t s0 = smem_u32(asmem);
    const uint32_t sQh = s0, sQl = s0 + 16384;
    const uint32_t kv0 = s0 + 32768;          // 2 buffers x 32KB: K,V

    const int tid = threadIdx.x, lane = tid & 31, wid = tid >> 5;
    const int qt = (gridDim.x - 1) - blockIdx.x;   // heavy tiles first
    const int bh = blockIdx.y;
    const int b  = bh >> 4, h = bh & 15;
    const float SCL = 0.125f * 1.4426950408889634f;

    const size_t tokbase = (size_t)b * T_SEQ;
    const size_t headoff = (size_t)h * HD;

    // ---- stage Q (hi+lo) + K/V tile 0
    {
        const __half* gh = qhi + (tokbase + qt * 128) * CDIM + headoff;
        const __half* gl = qlo + (tokbase + qt * 128) * CDIM + headoff;
#pragma unroll
        for (int i = 0; i < 4; ++i) {
            int idx = tid + i * 256;
            int r = idx >> 3, c = idx & 7;
            uint32_t sw = r * 128 + ((c ^ (r & 7)) << 4);
            asm volatile("cp.async.cg.shared.global [%0], [%1], 16;"
                         :: "r"(sQh + sw), "l"(gh + (size_t)r * CDIM + c * 8));
            asm volatile("cp.async.cg.shared.global [%0], [%1], 16;"
                         :: "r"(sQl + sw), "l"(gl + (size_t)r * CDIM + c * 8));
        }
    }
    stage_kv(kv0, k16, v16, tokbase * CDIM + headoff, tid);

    uint32_t qhf[4][4], qlf[4][4];
    float o[8][4];
#pragma unroll
    for (int i = 0; i < 8; ++i)
#pragma unroll
        for (int j = 0; j < 4; ++j) o[i][j] = 0.0f;
    float m_[2] = { -1e30f, -1e30f };
    float l_[2] = { 0.0f, 0.0f };

    const int b_rb = (lane & 7) + ((lane >> 4) << 3);
    const int b_kc = (lane >> 3) & 1;
    const int v_rb = (lane & 7) + (((lane >> 3) & 1) << 3);
    const int v_cs = lane >> 4;

    for (int kt = 0; kt <= qt; ++kt) {
        const int cur = kt & 1;
        const uint32_t kvb = kv0 + cur * 32768;
        if (kt < qt) {
            stage_kv(kv0 + (cur ^ 1) * 32768, k16, v16,
                     (tokbase + (size_t)(kt + 1) * 128) * CDIM + headoff, tid);
            asm volatile("cp.async.wait_group 1;" ::: "memory");
        } else {
            asm volatile("cp.async.wait_group 0;" ::: "memory");
        }
        __syncthreads();

        if (kt == 0) {   // Q fragments now resident
            const int a_r  = wid * 16 + (lane & 7) + ((lane >> 3) & 1) * 8;
            const int a_kc = lane >> 4;
#pragma unroll
            for (int ks = 0; ks < 4; ++ks) {
                const int ch = ks * 2 + a_kc;
                uint32_t sw = a_r * 128 + ((ch ^ (a_r & 7)) << 4);
                ldsm4(qhf[ks][0], qhf[ks][1], qhf[ks][2], qhf[ks][3], sQh + sw);
                ldsm4(qlf[ks][0], qlf[ks][1], qlf[ks][2], qlf[ks][3], sQl + sw);
            }
        }

        const uint32_t sK = kvb, sV = kvb + 16384;

        // ---- S = (Qh+Ql) K^T
        float sc[16][4];
#pragma unroll
        for (int t = 0; t < 16; ++t)
#pragma unroll
            for (int j = 0; j < 4; ++j) sc[t][j] = 0.0f;

#pragma unroll
        for (int ks = 0; ks < 4; ++ks) {
#pragma unroll
            for (int g = 0; g < 8; ++g) {
                const int r = g * 16 + b_rb;
                const int ch = ks * 2 + b_kc;
                uint32_t sw = r * 128 + ((ch ^ (r & 7)) << 4);
                uint32_t k0, k1, k2, k3;
                ldsm4(k0, k1, k2, k3, sK + sw);
                mma_f16(sc[2 * g],     qhf[ks], k0, k1);
                mma_f16(sc[2 * g],     qlf[ks], k0, k1);
                mma_f16(sc[2 * g + 1], qhf[ks], k2, k3);
                mma_f16(sc[2 * g + 1], qlf[ks], k2, k3);
            }
        }

        // ---- scale + causal mask (diagonal tile only)
        const bool diag = (kt == qt);
#pragma unroll
        for (int t = 0; t < 16; ++t)
#pragma unroll
            for (int j = 0; j < 4; ++j) {
                float v = sc[t][j] * SCL;
                if (diag) {
                    const int col = t * 8 + ((lane & 3) << 1) + (j & 1);
                    const int row = (wid << 4) + (lane >> 2) + ((j >> 1) << 3);
                    if (col > row) v = -1e30f;
                }
                sc[t][j] = v;
            }

        // ---- online softmax (log2 domain)
#pragma unroll
        for (int hf = 0; hf < 2; ++hf) {
            float mx = -1e30f;
#pragma unroll
            for (int t = 0; t < 16; ++t)
                mx = fmaxf(mx, fmaxf(sc[t][2 * hf], sc[t][2 * hf + 1]));
            mx = fmaxf(mx, __shfl_xor_sync(0xffffffffu, mx, 1));
            mx = fmaxf(mx, __shfl_xor_sync(0xffffffffu, mx, 2));
            const float mn = fmaxf(m_[hf], mx);
            const float corr = ex2f(m_[hf] - mn);
            float rs = 0.0f;
#pragma unroll
            for (int t = 0; t < 16; ++t) {
                float p0 = ex2f(sc[t][2 * hf]     - mn);
                float p1 = ex2f(sc[t][2 * hf + 1] - mn);
                sc[t][2 * hf] = p0; sc[t][2 * hf + 1] = p1;
                rs += p0 + p1;
            }
            rs += __shfl_xor_sync(0xffffffffu, rs, 1);
            rs += __shfl_xor_sync(0xffffffffu, rs, 2);
            l_[hf] = l_[hf] * corr + rs;
            m_[hf] = mn;
#pragma unroll
            for (int nt = 0; nt < 8; ++nt) {
                o[nt][2 * hf]     *= corr;
                o[nt][2 * hf + 1] *= corr;
            }
        }

        // ---- O += (Ph+Pl) V ; P fragments built in registers
#pragma unroll
        for (int ks2 = 0; ks2 < 8; ++ks2) {
            uint32_t ph[4], pl[4];
            split2h(sc[2 * ks2][0],     sc[2 * ks2][1],     ph[0], pl[0]);
            split2h(sc[2 * ks2][2],     sc[2 * ks2][3],     ph[1], pl[1]);
            split2h(sc[2 * ks2 + 1][0], sc[2 * ks2 + 1][1], ph[2], pl[2]);
            split2h(sc[2 * ks2 + 1][2], sc[2 * ks2 + 1][3], ph[3], pl[3]);
#pragma unroll
            for (int ng = 0; ng < 4; ++ng) {
                const int r = ks2 * 16 + v_rb;
                const int ch = ng * 2 + v_cs;
                uint32_t sw = r * 128 + ((ch ^ (r & 7)) << 4);
                uint32_t v0, v1, v2, v3;
                ldsm4t(v0, v1, v2, v3, sV + sw);
                mma_f16(o[2 * ng],     ph, v0, v1);
                mma_f16(o[2 * ng],     pl, v0, v1);
                mma_f16(o[2 * ng + 1], ph, v2, v3);
                mma_f16(o[2 * ng + 1], pl, v2, v3);
            }
        }
        __syncthreads();
    }

    // ---- epilogue: normalize, split hi/lo, store
#pragma unroll
    for (int hf = 0; hf < 2; ++hf) {
        const float inv = 1.0f / l_[hf];
        const int row = qt * 128 + wid * 16 + (lane >> 2) + hf * 8;
        __half* oh = ohi + (tokbase + row) * CDIM + headoff;
        __half* ol = olo + (tokbase + row) * CDIM + headoff;
#pragma unroll
        for (int nt = 0; nt < 8; ++nt) {
            const int col = nt * 8 + (lane & 3) * 2;
            float f0 = o[nt][2 * hf]     * inv;
            float f1 = o[nt][2 * hf + 1] * inv;
            uint32_t hp, lp;
            split2h(f0, f1, hp, lp);
            *(uint32_t*)(oh + col) = hp;
            *(uint32_t*)(ol + col) = lp;
        }
    }
}

// ---------------------------------------------------------------------------
// Launch.  Inputs: 0:x 1:mask 2:context_vector 3:w_q 4:w_k 5:w_v 6:w_o 7:b_o
//                  8:context_bias    out: f32 [2,2048,1024]
// ---------------------------------------------------------------------------
extern "C" void kernel_launch(void* const* d_in, const int* in_sizes, int n_in,
                              void* d_out, int out_size)
{
    (void)in_sizes; (void)n_in; (void)out_size;
    const float* x  = (const float*)d_in[0];
    const float* cv = (const float*)d_in[2];
    const float* wq = (const float*)d_in[3];
    const float* wk = (const float*)d_in[4];
    const float* wv = (const float*)d_in[5];
    const float* wo = (const float*)d_in[6];
    const float* bo = (const float*)d_in[7];
    const float* cb = (const float*)d_in[8];
    float* out = (float*)d_out;

    __half *xh, *xl, *wq16, *wk16, *wv16, *wo16;
    __half *qh, *ql, *k16, *v16, *ah, *al;
    cudaGetSymbolAddress((void**)&xh,   g_xhi);  cudaGetSymbolAddress((void**)&xl,   g_xlo);
    cudaGetSymbolAddress((void**)&wq16, g_wq16); cudaGetSymbolAddress((void**)&wk16, g_wk16);
    cudaGetSymbolAddress((void**)&wv16, g_wv16); cudaGetSymbolAddress((void**)&wo16, g_wo16);
    cudaGetSymbolAddress((void**)&qh,   g_qhi);  cudaGetSymbolAddress((void**)&ql,   g_qlo);
    cudaGetSymbolAddress((void**)&k16,  g_k16);  cudaGetSymbolAddress((void**)&v16,  g_v16);
    cudaGetSymbolAddress((void**)&ah,   g_ahi);  cudaGetSymbolAddress((void**)&al,   g_alo);

    const int gemm_smem = 6 * TILEB;                 // 98304
    cudaFuncSetAttribute(gemm_qkv, cudaFuncAttributeMaxDynamicSharedMemorySize, gemm_smem);
    cudaFuncSetAttribute(gemm_out, cudaFuncAttributeMaxDynamicSharedMemorySize, gemm_smem);
    const int attn_smem = 2 * 16384 + 2 * 32768;     // 98304
    cudaFuncSetAttribute(attn_mma, cudaFuncAttributeMaxDynamicSharedMemorySize, attn_smem);

    const int NX4 = MTOK * CDIM / 4;
    const int NW4 = CDIM * CDIM / 4;

    split_f16<<<1024, 256>>>(x, xh, xl, NX4);
    cvt_f16<<<512, 256>>>(wq, wq16, NW4);
    cvt_f16<<<512, 256>>>(wk, wk16, NW4);
    cvt_f16<<<512, 256>>>(wv, wv16, NW4);
    cvt_f16<<<512, 256>>>(wo, wo16, NW4);

    gemm_qkv<<<dim3(24, MTOK / 128), 256, gemm_smem>>>(
        xh, xl, wq16, wk16, wv16, qh, ql, k16, v16, cv, cb);

    attn_mma<<<dim3(T_SEQ / 128, NB * NH), 256, attn_smem>>>(
        qh, ql, k16, v16, ah, al);

    gemm_out<<<dim3(CDIM / 128, MTOK / 128), 256, gemm_smem>>>(
        ah, al, wo16, out, bo);
}

// round 8
// speedup vs baseline: 1.8808x; 1.2185x over previous
#include <cuda_runtime.h>
#include <cuda_fp16.h>
#include <math.h>
#include <stdint.h>

#define T_SEQ 2048
#define CDIM  1024
#define NB    2
#define NH    16
#define HD    64
#define MTOK  (NB * T_SEQ)   // 4096 token rows

// ---------------------------------------------------------------------------
// Scratch (static device globals)
// ---------------------------------------------------------------------------
__device__ __half g_xhi[(size_t)MTOK * CDIM];
__device__ __half g_xlo[(size_t)MTOK * CDIM];
__device__ __half g_wq16[(size_t)CDIM * CDIM];
__device__ __half g_wk16[(size_t)CDIM * CDIM];
__device__ __half g_wv16[(size_t)CDIM * CDIM];
__device__ __half g_wo16[(size_t)CDIM * CDIM];
__device__ __half g_qhi[(size_t)MTOK * CDIM];
__device__ __half g_qlo[(size_t)MTOK * CDIM];
__device__ __half g_k16[(size_t)MTOK * CDIM];
__device__ __half g_v16[(size_t)MTOK * CDIM];
__device__ __half g_ahi[(size_t)MTOK * CDIM];
__device__ __half g_alo[(size_t)MTOK * CDIM];

// ---------------------------------------------------------------------------
// Helpers
// ---------------------------------------------------------------------------
__device__ __forceinline__ uint32_t smem_u32(const void* p) {
    uint32_t a;
    asm("{ .reg .u64 t; cvta.to.shared.u64 t, %1; cvt.u32.u64 %0, t; }"
        : "=r"(a) : "l"(p));
    return a;
}
__device__ __forceinline__ float ex2f(float x) {
    float y; asm("ex2.approx.ftz.f32 %0, %1;" : "=f"(y) : "f"(x)); return y;
}
__device__ __forceinline__ void ldsm4(uint32_t& r0, uint32_t& r1,
                                      uint32_t& r2, uint32_t& r3, uint32_t addr) {
    asm volatile("ldmatrix.sync.aligned.m8n8.x4.shared.b16 {%0,%1,%2,%3}, [%4];"
                 : "=r"(r0), "=r"(r1), "=r"(r2), "=r"(r3) : "r"(addr));
}
__device__ __forceinline__ void ldsm4t(uint32_t& r0, uint32_t& r1,
                                       uint32_t& r2, uint32_t& r3, uint32_t addr) {
    asm volatile("ldmatrix.sync.aligned.m8n8.x4.trans.shared.b16 {%0,%1,%2,%3}, [%4];"
                 : "=r"(r0), "=r"(r1), "=r"(r2), "=r"(r3) : "r"(addr));
}
__device__ __forceinline__ void mma_f16(float* c, const uint32_t* a,
                                        uint32_t b0, uint32_t b1) {
    asm volatile(
        "mma.sync.aligned.m16n8k16.row.col.f32.f16.f16.f32 "
        "{%0,%1,%2,%3}, {%4,%5,%6,%7}, {%8,%9}, {%0,%1,%2,%3};"
        : "+f"(c[0]), "+f"(c[1]), "+f"(c[2]), "+f"(c[3])
        : "r"(a[0]), "r"(a[1]), "r"(a[2]), "r"(a[3]), "r"(b0), "r"(b1));
}
__device__ __forceinline__ uint32_t packh(float f0, float f1) {
    __half2 h = __floats2half2_rn(f0, f1);
    return *(uint32_t*)&h;
}
__device__ __forceinline__ void split2h(float f0, float f1, uint32_t& hp, uint32_t& lp) {
    hp = packh(f0, f1);
    __half2 h = *(__half2*)&hp;
    lp = packh(f0 - __low2float(h), f1 - __high2float(h));
}

// ---------------------------------------------------------------------------
// fp32 -> fp16 hi + residual;  fused 4-weight fp32 -> fp16 convert
// ---------------------------------------------------------------------------
__global__ __launch_bounds__(256) void split_f16(
    const float* __restrict__ in, __half* __restrict__ hi,
    __half* __restrict__ lo, int n4)
{
    int i = blockIdx.x * blockDim.x + threadIdx.x;
    const int stride = gridDim.x * blockDim.x;
    for (; i < n4; i += stride) {
        float4 v = *(const float4*)(in + (size_t)i * 4);
        uint32_t h01, l01, h23, l23;
        split2h(v.x, v.y, h01, l01);
        split2h(v.z, v.w, h23, l23);
        uint2 hh; hh.x = h01; hh.y = h23;
        uint2 ll; ll.x = l01; ll.y = l23;
        *(uint2*)(hi + (size_t)i * 4) = hh;
        *(uint2*)(lo + (size_t)i * 4) = ll;
    }
}
__global__ __launch_bounds__(256) void cvt_f16_4(
    const float* __restrict__ w0, const float* __restrict__ w1,
    const float* __restrict__ w2, const float* __restrict__ w3,
    __half* __restrict__ o0, __half* __restrict__ o1,
    __half* __restrict__ o2, __half* __restrict__ o3, int n4)
{
    const float* in  = (blockIdx.y == 0) ? w0 : (blockIdx.y == 1) ? w1 :
                       (blockIdx.y == 2) ? w2 : w3;
    __half* out = (blockIdx.y == 0) ? o0 : (blockIdx.y == 1) ? o1 :
                  (blockIdx.y == 2) ? o2 : o3;
    int i = blockIdx.x * blockDim.x + threadIdx.x;
    const int stride = gridDim.x * blockDim.x;
    for (; i < n4; i += stride) {
        float4 v = *(const float4*)(in + (size_t)i * 4);
        uint2 hh; hh.x = packh(v.x, v.y); hh.y = packh(v.z, v.w);
        *(uint2*)(out + (size_t)i * 4) = hh;
    }
}

// ---------------------------------------------------------------------------
// GEMM core, templated on whether A is 2-term (Ah+Al) or single (Ah).
// CTA 128x128, 8 warps (32x64 warp tile), K-tile 64, double buffer.
// ---------------------------------------------------------------------------
#define NT16  16
#define TILEB 16384       // 128 rows * 128B

__device__ __forceinline__ void stage_g(
    uint32_t s, const __half* __restrict__ G, int r0, int koff, int tid)
{
#pragma unroll
    for (int i = 0; i < 4; ++i) {
        int idx = tid + i * 256;
        int r = idx >> 3, c = idx & 7;
        uint32_t sw = r * 128 + ((c ^ (r & 7)) << 4);
        const __half* g = G + (size_t)(r0 + r) * CDIM + koff + c * 8;
        asm volatile("cp.async.cg.shared.global [%0], [%1], 16;"
                     :: "r"(s + sw), "l"(g));
    }
}

template <bool SPLIT>
__device__ __forceinline__ void gemm_core(
    uint32_t s0,
    const __half* Ah, const __half* Al, const __half* B16,
    int m0, int n0, int tid, int lane, int wm, int wn,
    float acc[2][8][4])
{
    const int NBUF = SPLIT ? 3 : 2;
    uint32_t sAh[2] = { s0,                      s0 + NBUF * TILEB };
    uint32_t sAl[2] = { s0 + TILEB,              s0 + (NBUF + 1) * TILEB };  // SPLIT only
    uint32_t sB [2] = { s0 + (NBUF - 1) * TILEB, s0 + (2 * NBUF - 1) * TILEB };

    const int a_r  = wm + (lane & 7) + ((lane >> 3) & 1) * 8;
    const int a_kc = lane >> 4;
    const int b_r  = wn + (lane & 7) + (lane >> 4) * 8;
    const int b_kc = (lane >> 3) & 1;

    stage_g(sAh[0], Ah, m0, 0, tid);
    if (SPLIT) stage_g(sAl[0], Al, m0, 0, tid);
    stage_g(sB[0], B16, n0, 0, tid);
    asm volatile("cp.async.commit_group;" ::: "memory");

    for (int t = 0; t < NT16; ++t) {
        const int cur = t & 1, nxt = cur ^ 1;
        if (t + 1 < NT16) {
            const int ko = (t + 1) * 64;
            stage_g(sAh[nxt], Ah, m0, ko, tid);
            if (SPLIT) stage_g(sAl[nxt], Al, m0, ko, tid);
            stage_g(sB[nxt], B16, n0, ko, tid);
            asm volatile("cp.async.commit_group;" ::: "memory");
            asm volatile("cp.async.wait_group 1;" ::: "memory");
        } else {
            asm volatile("cp.async.wait_group 0;" ::: "memory");
        }
        __syncthreads();

#pragma unroll
        for (int ks = 0; ks < 4; ++ks) {
            uint32_t ah[2][4], al[2][4];
#pragma unroll
            for (int mt = 0; mt < 2; ++mt) {
                const int r = a_r + mt * 16;
                uint32_t off = r * 128 + (((ks * 2 + a_kc) ^ (r & 7)) << 4);
                ldsm4(ah[mt][0], ah[mt][1], ah[mt][2], ah[mt][3], sAh[cur] + off);
                if (SPLIT)
                    ldsm4(al[mt][0], al[mt][1], al[mt][2], al[mt][3], sAl[cur] + off);
            }
            uint32_t bf[8][2];
#pragma unroll
            for (int p = 0; p < 4; ++p) {
                const int r = b_r + p * 16;
                uint32_t off = r * 128 + (((ks * 2 + b_kc) ^ (r & 7)) << 4);
                ldsm4(bf[2 * p][0], bf[2 * p][1], bf[2 * p + 1][0], bf[2 * p + 1][1],
                      sB[cur] + off);
            }
#pragma unroll
            for (int mt = 0; mt < 2; ++mt)
#pragma unroll
                for (int nt = 0; nt < 8; ++nt) {
                    mma_f16(acc[mt][nt], ah[mt], bf[nt][0], bf[nt][1]);
                    if (SPLIT)
                        mma_f16(acc[mt][nt], al[mt], bf[nt][0], bf[nt][1]);
                }
        }
        __syncthreads();
    }
}

// Fused QKV projection: grid.x = 24 (8 n-blocks x {q,k,v}).
// Q: X 2-term -> fp16 hi/lo out.  K,V: Xh single -> fp16 out.
__global__ __launch_bounds__(256) void gemm_qkv(
    const __half* __restrict__ xh, const __half* __restrict__ xl,
    const __half* __restrict__ wq16, const __half* __restrict__ wk16,
    const __half* __restrict__ wv16,
    __half* __restrict__ qh, __half* __restrict__ ql,
    __half* __restrict__ k16, __half* __restrict__ v16,
    const float* __restrict__ cv, const float* __restrict__ cb)
{
    extern __shared__ char gsm[];
    uint32_t s0 = smem_u32(gsm);

    const int tid = threadIdx.x, lane = tid & 31, wid = tid >> 5;
    const int wm = (wid >> 1) * 32, wn = (wid & 1) * 64;
    const int wsel = blockIdx.x >> 3;
    const int n0 = (blockIdx.x & 7) * 128;
    const int m0 = blockIdx.y * 128;

    float acc[2][8][4];
#pragma unroll
    for (int a = 0; a < 2; ++a)
#pragma unroll
        for (int b = 0; b < 8; ++b)
#pragma unroll
            for (int c = 0; c < 4; ++c) acc[a][b][c] = 0.0f;

    if (wsel == 0)
        gemm_core<true >(s0, xh, xl, wq16, m0, n0, tid, lane, wm, wn, acc);
    else if (wsel == 1)
        gemm_core<false>(s0, xh, xl, wk16, m0, n0, tid, lane, wm, wn, acc);
    else
        gemm_core<false>(s0, xh, xl, wv16, m0, n0, tid, lane, wm, wn, acc);

    const int er = lane >> 2, ec = (lane & 3) * 2;
#pragma unroll
    for (int mt = 0; mt < 2; ++mt)
#pragma unroll
        for (int half = 0; half < 2; ++half) {
            const int row = m0 + wm + mt * 16 + er + half * 8;
#pragma unroll
            for (int nt = 0; nt < 8; ++nt) {
                const int col = n0 + wn + nt * 8 + ec;
                float v0 = acc[mt][nt][half * 2 + 0];
                float v1 = acc[mt][nt][half * 2 + 1];
                if (wsel == 0) {
                    const float* cvr = cv + (size_t)row * CDIM;
                    v0 += cb[col]     * cvr[col];
                    v1 += cb[col + 1] * cvr[col + 1];
                    uint32_t hp, lp;
                    split2h(v0, v1, hp, lp);
                    *(uint32_t*)(qh + (size_t)row * CDIM + col) = hp;
                    *(uint32_t*)(ql + (size_t)row * CDIM + col) = lp;
                } else {
                    __half* O = (wsel == 1) ? k16 : v16;
                    *(uint32_t*)(O + (size_t)row * CDIM + col) = packh(v0, v1);
                }
            }
        }
}

// Output projection: A 2-term, fp32 out + bias
__global__ __launch_bounds__(256) void gemm_out(
    const __half* __restrict__ ah, const __half* __restrict__ al,
    const __half* __restrict__ wo16,
    float* __restrict__ Y, const float* __restrict__ bias)
{
    extern __shared__ char gsm[];
    uint32_t s0 = smem_u32(gsm);

    const int tid = threadIdx.x, lane = tid & 31, wid = tid >> 5;
    const int wm = (wid >> 1) * 32, wn = (wid & 1) * 64;
    const int m0 = blockIdx.y * 128, n0 = blockIdx.x * 128;

    float acc[2][8][4];
#pragma unroll
    for (int a = 0; a < 2; ++a)
#pragma unroll
        for (int b = 0; b < 8; ++b)
#pragma unroll
            for (int c = 0; c < 4; ++c) acc[a][b][c] = 0.0f;

    gemm_core<true>(s0, ah, al, wo16, m0, n0, tid, lane, wm, wn, acc);

    const int er = lane >> 2, ec = (lane & 3) * 2;
#pragma unroll
    for (int mt = 0; mt < 2; ++mt)
#pragma unroll
        for (int half = 0; half < 2; ++half) {
            const int row = m0 + wm + mt * 16 + er + half * 8;
            float* yrow = Y + (size_t)row * CDIM;
#pragma unroll
            for (int nt = 0; nt < 8; ++nt) {
                const int col = n0 + wn + nt * 8 + ec;
                float2 f;
                f.x = acc[mt][nt][half * 2 + 0] + bias[col];
                f.y = acc[mt][nt][half * 2 + 1] + bias[col + 1];
                *(float2*)(yrow + col) = f;
            }
        }
}

// ---------------------------------------------------------------------------
// Causal flash attention, fp16 mma. Q split 2-term for S; K, V, P single.
// CTA: 128 q-rows; 8 warps of 16 q-rows x 128 k-cols. K/V double-buffered.
// ---------------------------------------------------------------------------
__device__ __forceinline__ void stage_kv(
    uint32_t kvb, const __half* __restrict__ k16, const __half* __restrict__ v16,
    size_t rb, int tid)
{
#pragma unroll
    for (int i = 0; i < 4; ++i) {
        int idx = tid + i * 256;
        int r = idx >> 3, c = idx & 7;
        uint32_t sw = r * 128 + ((c ^ (r & 7)) << 4);
        size_t g = rb + (size_t)r * CDIM + c * 8;
        asm volatile("cp.async.cg.shared.global [%0], [%1], 16;" :: "r"(kvb + sw),         "l"(k16 + g));
        asm volatile("cp.async.cg.shared.global [%0], [%1], 16;" :: "r"(kvb + 16384 + sw), "l"(v16 + g));
    }
    asm volatile("cp.async.commit_group;" ::: "memory");
}

__global__ __launch_bounds__(256) void attn_mma(
    const __half* __restrict__ qhi, const __half* __restrict__ qlo,
    const __half* __restrict__ k16, const __half* __restrict__ v16,
    __half* __restrict__ ohi, __half* __restrict__ olo)
{
    extern __shared__ char asmem[];
    const uint32_t s0 = smem_u32(asmem);
    const uint32_t sQh = s0, sQl = s0 + 16384;
    const uint32_t kv0 = s0 + 32768;          // 2 buffers x 32KB: K,V

    const int tid = threadIdx.x, lane = tid & 31, wid = tid >> 5;
    const int qt = (gridDim.x - 1) - blockIdx.x;   // heavy tiles first
    const int bh = blockIdx.y;
    const int b  = bh >> 4, h = bh & 15;
    const float SCL = 0.125f * 1.4426950408889634f;

    const size_t tokbase = (size_t)b * T_SEQ;
    const size_t headoff = (size_t)h * HD;

    // ---- stage Q (hi+lo) + K/V tile 0
    {
        const __half* gh = qhi + (tokbase + qt * 128) * CDIM + headoff;
        const __half* gl = qlo + (tokbase + qt * 128) * CDIM + headoff;
#pragma unroll
        for (int i = 0; i < 4; ++i) {
            int idx = tid + i * 256;
            int r = idx >> 3, c = idx & 7;
            uint32_t sw = r * 128 + ((c ^ (r & 7)) << 4);
            asm volatile("cp.async.cg.shared.global [%0], [%1], 16;"
                         :: "r"(sQh + sw), "l"(gh + (size_t)r * CDIM + c * 8));
            asm volatile("cp.async.cg.shared.global [%0], [%1], 16;"
                         :: "r"(sQl + sw), "l"(gl + (size_t)r * CDIM + c * 8));
        }
    }
    stage_kv(kv0, k16, v16, tokbase * CDIM + headoff, tid);

    uint32_t qhf[4][4], qlf[4][4];
    float o[8][4];
#pragma unroll
    for (int i = 0; i < 8; ++i)
#pragma unroll
        for (int j = 0; j < 4; ++j) o[i][j] = 0.0f;
    float m_[2] = { -1e30f, -1e30f };
    float l_[2] = { 0.0f, 0.0f };

    const int b_rb = (lane & 7) + ((lane >> 4) << 3);
    const int b_kc = (lane >> 3) & 1;
    const int v_rb = (lane & 7) + (((lane >> 3) & 1) << 3);
    const int v_cs = lane >> 4;

    for (int kt = 0; kt <= qt; ++kt) {
        const int cur = kt & 1;
        const uint32_t kvb = kv0 + cur * 32768;
        if (kt < qt) {
            stage_kv(kv0 + (cur ^ 1) * 32768, k16, v16,
                     (tokbase + (size_t)(kt + 1) * 128) * CDIM + headoff, tid);
            asm volatile("cp.async.wait_group 1;" ::: "memory");
        } else {
            asm volatile("cp.async.wait_group 0;" ::: "memory");
        }
        __syncthreads();

        if (kt == 0) {   // Q fragments now resident
            const int a_r  = wid * 16 + (lane & 7) + ((lane >> 3) & 1) * 8;
            const int a_kc = lane >> 4;
#pragma unroll
            for (int ks = 0; ks < 4; ++ks) {
                const int ch = ks * 2 + a_kc;
                uint32_t sw = a_r * 128 + ((ch ^ (a_r & 7)) << 4);
                ldsm4(qhf[ks][0], qhf[ks][1], qhf[ks][2], qhf[ks][3], sQh + sw);
                ldsm4(qlf[ks][0], qlf[ks][1], qlf[ks][2], qlf[ks][3], sQl + sw);
            }
        }

        const uint32_t sK = kvb, sV = kvb + 16384;

        // ---- S = (Qh+Ql) K^T
        float sc[16][4];
#pragma unroll
        for (int t = 0; t < 16; ++t)
#pragma unroll
            for (int j = 0; j < 4; ++j) sc[t][j] = 0.0f;

#pragma unroll
        for (int ks = 0; ks < 4; ++ks) {
#pragma unroll
            for (int g = 0; g < 8; ++g) {
                const int r = g * 16 + b_rb;
                const int ch = ks * 2 + b_kc;
                uint32_t sw = r * 128 + ((ch ^ (r & 7)) << 4);
                uint32_t k0, k1, k2, k3;
                ldsm4(k0, k1, k2, k3, sK + sw);
                mma_f16(sc[2 * g],     qhf[ks], k0, k1);
                mma_f16(sc[2 * g],     qlf[ks], k0, k1);
                mma_f16(sc[2 * g + 1], qhf[ks], k2, k3);
                mma_f16(sc[2 * g + 1], qlf[ks], k2, k3);
            }
        }

        // ---- scale + causal mask (diagonal tile only)
        const bool diag = (kt == qt);
#pragma unroll
        for (int t = 0; t < 16; ++t)
#pragma unroll
            for (int j = 0; j < 4; ++j) {
                float v = sc[t][j] * SCL;
                if (diag) {
                    const int col = t * 8 + ((lane & 3) << 1) + (j & 1);
                    const int row = (wid << 4) + (lane >> 2) + ((j >> 1) << 3);
                    if (col > row) v = -1e30f;
                }
                sc[t][j] = v;
            }

        // ---- online softmax (log2 domain)
#pragma unroll
        for (int hf = 0; hf < 2; ++hf) {
            float mx = -1e30f;
#pragma unroll
            for (int t = 0; t < 16; ++t)
                mx = fmaxf(mx, fmaxf(sc[t][2 * hf], sc[t][2 * hf + 1]));
            mx = fmaxf(mx, __shfl_xor_sync(0xffffffffu, mx, 1));
            mx = fmaxf(mx, __shfl_xor_sync(0xffffffffu, mx, 2));
            const float mn = fmaxf(m_[hf], mx);
            const float corr = ex2f(m_[hf] - mn);
            float rs = 0.0f;
#pragma unroll
            for (int t = 0; t < 16; ++t) {
                float p0 = ex2f(sc[t][2 * hf]     - mn);
                float p1 = ex2f(sc[t][2 * hf + 1] - mn);
                sc[t][2 * hf] = p0; sc[t][2 * hf + 1] = p1;
                rs += p0 + p1;
            }
            rs += __shfl_xor_sync(0xffffffffu, rs, 1);
            rs += __shfl_xor_sync(0xffffffffu, rs, 2);
            l_[hf] = l_[hf] * corr + rs;
            m_[hf] = mn;
#pragma unroll
            for (int nt = 0; nt < 8; ++nt) {
                o[nt][2 * hf]     *= corr;
                o[nt][2 * hf + 1] *= corr;
            }
        }

        // ---- O += P V (P single fp16, fragments in registers)
#pragma unroll
        for (int ks2 = 0; ks2 < 8; ++ks2) {
            uint32_t ph[4];
            ph[0] = packh(sc[2 * ks2][0],     sc[2 * ks2][1]);
            ph[1] = packh(sc[2 * ks2][2],     sc[2 * ks2][3]);
            ph[2] = packh(sc[2 * ks2 + 1][0], sc[2 * ks2 + 1][1]);
            ph[3] = packh(sc[2 * ks2 + 1][2], sc[2 * ks2 + 1][3]);
#pragma unroll
            for (int ng = 0; ng < 4; ++ng) {
                const int r = ks2 * 16 + v_rb;
                const int ch = ng * 2 + v_cs;
                uint32_t sw = r * 128 + ((ch ^ (r & 7)) << 4);
                uint32_t v0, v1, v2, v3;
                ldsm4t(v0, v1, v2, v3, sV + sw);
                mma_f16(o[2 * ng],     ph, v0, v1);
                mma_f16(o[2 * ng + 1], ph, v2, v3);
            }
        }
        __syncthreads();
    }

    // ---- epilogue: normalize, split hi/lo, store
#pragma unroll
    for (int hf = 0; hf < 2; ++hf) {
        const float inv = 1.0f / l_[hf];
        const int row = qt * 128 + wid * 16 + (lane >> 2) + hf * 8;
        __half* oh = ohi + (tokbase + row) * CDIM + headoff;
        __half* ol = olo + (tokbase + row) * CDIM + headoff;
#pragma unroll
        for (int nt = 0; nt < 8; ++nt) {
            const int col = nt * 8 + (lane & 3) * 2;
            float f0 = o[nt][2 * hf]     * inv;
            float f1 = o[nt][2 * hf + 1] * inv;
            uint32_t hp, lp;
            split2h(f0, f1, hp, lp);
            *(uint32_t*)(oh + col) = hp;
            *(uint32_t*)(ol + col) = lp;
        }
    }
}

// ---------------------------------------------------------------------------
// Launch.  Inputs: 0:x 1:mask 2:context_vector 3:w_q 4:w_k 5:w_v 6:w_o 7:b_o
//                  8:context_bias    out: f32 [2,2048,1024]
// ---------------------------------------------------------------------------
extern "C" void kernel_launch(void* const* d_in, const int* in_sizes, int n_in,
                              void* d_out, int out_size)
{
    (void)in_sizes; (void)n_in; (void)out_size;
    const float* x  = (const float*)d_in[0];
    const float* cv = (const float*)d_in[2];
    const float* wq = (const float*)d_in[3];
    const float* wk = (const float*)d_in[4];
    const float* wv = (const float*)d_in[5];
    const float* wo = (const float*)d_in[6];
    const float* bo = (const float*)d_in[7];
    const float* cb = (const float*)d_in[8];
    float* out = (float*)d_out;

    __half *xh, *xl, *wq16, *wk16, *wv16, *wo16;
    __half *qh, *ql, *k16, *v16, *ah, *al;
    cudaGetSymbolAddress((void**)&xh,   g_xhi);  cudaGetSymbolAddress((void**)&xl,   g_xlo);
    cudaGetSymbolAddress((void**)&wq16, g_wq16); cudaGetSymbolAddress((void**)&wk16, g_wk16);
    cudaGetSymbolAddress((void**)&wv16, g_wv16); cudaGetSymbolAddress((void**)&wo16, g_wo16);
    cudaGetSymbolAddress((void**)&qh,   g_qhi);  cudaGetSymbolAddress((void**)&ql,   g_qlo);
    cudaGetSymbolAddress((void**)&k16,  g_k16);  cudaGetSymbolAddress((void**)&v16,  g_v16);
    cudaGetSymbolAddress((void**)&ah,   g_ahi);  cudaGetSymbolAddress((void**)&al,   g_alo);

    const int gemm_smem = 6 * TILEB;                 // 98304 (max of both variants)
    cudaFuncSetAttribute(gemm_qkv, cudaFuncAttributeMaxDynamicSharedMemorySize, gemm_smem);
    cudaFuncSetAttribute(gemm_out, cudaFuncAttributeMaxDynamicSharedMemorySize, gemm_smem);
    const int attn_smem = 2 * 16384 + 2 * 32768;     // 98304
    cudaFuncSetAttribute(attn_mma, cudaFuncAttributeMaxDynamicSharedMemorySize, attn_smem);

    const int NX4 = MTOK * CDIM / 4;
    const int NW4 = CDIM * CDIM / 4;

    split_f16<<<1024, 256>>>(x, xh, xl, NX4);
    cvt_f16_4<<<dim3(256, 4), 256>>>(wq, wk, wv, wo, wq16, wk16, wv16, wo16, NW4);

    gemm_qkv<<<dim3(24, MTOK / 128), 256, gemm_smem>>>(
        xh, xl, wq16, wk16, wv16, qh, ql, k16, v16, cv, cb);

    attn_mma<<<dim3(T_SEQ / 128, NB * NH), 256, attn_smem>>>(
        qh, ql, k16, v16, ah, al);

    gemm_out<<<dim3(CDIM / 128, MTOK / 128), 256, gemm_smem>>>(
        ah, al, wo16, out, bo);
}

// round 9
// speedup vs baseline: 2.8924x; 1.5378x over previous
#include <cuda_runtime.h>
#include <cuda_fp16.h>
#include <math.h>
#include <stdint.h>

#define T_SEQ 2048
#define CDIM  1024
#define NB    2
#define NH    16
#define HD    64
#define MTOK  (NB * T_SEQ)   // 4096 token rows

// ---------------------------------------------------------------------------
// Scratch (static device globals)
// ---------------------------------------------------------------------------
__device__ __half g_x16[(size_t)MTOK * CDIM];
__device__ __half g_wq16[(size_t)CDIM * CDIM];
__device__ __half g_wk16[(size_t)CDIM * CDIM];
__device__ __half g_wv16[(size_t)CDIM * CDIM];
__device__ __half g_wo16[(size_t)CDIM * CDIM];
__device__ __half g_q16[(size_t)MTOK * CDIM];
__device__ __half g_k16[(size_t)MTOK * CDIM];
__device__ __half g_v16[(size_t)MTOK * CDIM];
__device__ __half g_a16[(size_t)MTOK * CDIM];

// ---------------------------------------------------------------------------
// Helpers
// ---------------------------------------------------------------------------
__device__ __forceinline__ uint32_t smem_u32(const void* p) {
    uint32_t a;
    asm("{ .reg .u64 t; cvta.to.shared.u64 t, %1; cvt.u32.u64 %0, t; }"
        : "=r"(a) : "l"(p));
    return a;
}
__device__ __forceinline__ float ex2f(float x) {
    float y; asm("ex2.approx.ftz.f32 %0, %1;" : "=f"(y) : "f"(x)); return y;
}
__device__ __forceinline__ void ldsm4(uint32_t& r0, uint32_t& r1,
                                      uint32_t& r2, uint32_t& r3, uint32_t addr) {
    asm volatile("ldmatrix.sync.aligned.m8n8.x4.shared.b16 {%0,%1,%2,%3}, [%4];"
                 : "=r"(r0), "=r"(r1), "=r"(r2), "=r"(r3) : "r"(addr));
}
__device__ __forceinline__ void ldsm4t(uint32_t& r0, uint32_t& r1,
                                       uint32_t& r2, uint32_t& r3, uint32_t addr) {
    asm volatile("ldmatrix.sync.aligned.m8n8.x4.trans.shared.b16 {%0,%1,%2,%3}, [%4];"
                 : "=r"(r0), "=r"(r1), "=r"(r2), "=r"(r3) : "r"(addr));
}
__device__ __forceinline__ void mma_f16(float* c, const uint32_t* a,
                                        uint32_t b0, uint32_t b1) {
    asm volatile(
        "mma.sync.aligned.m16n8k16.row.col.f32.f16.f16.f32 "
        "{%0,%1,%2,%3}, {%4,%5,%6,%7}, {%8,%9}, {%0,%1,%2,%3};"
        : "+f"(c[0]), "+f"(c[1]), "+f"(c[2]), "+f"(c[3])
        : "r"(a[0]), "r"(a[1]), "r"(a[2]), "r"(a[3]), "r"(b0), "r"(b1));
}
__device__ __forceinline__ uint32_t packh(float f0, float f1) {
    __half2 h = __floats2half2_rn(f0, f1);
    return *(uint32_t*)&h;
}

// ---------------------------------------------------------------------------
// fp32 -> fp16 converts: x (grid.y==4) and the 4 weights, one launch
// ---------------------------------------------------------------------------
__global__ __launch_bounds__(256) void cvt_all(
    const float* __restrict__ x,
    const float* __restrict__ w0, const float* __restrict__ w1,
    const float* __restrict__ w2, const float* __restrict__ w3,
    __half* __restrict__ xo,
    __half* __restrict__ o0, __half* __restrict__ o1,
    __half* __restrict__ o2, __half* __restrict__ o3, int nw4, int nx4)
{
    const float* in; __half* out; int n4;
    if (blockIdx.y == 4) { in = x;  out = xo; n4 = nx4; }
    else {
        in  = (blockIdx.y == 0) ? w0 : (blockIdx.y == 1) ? w1 :
              (blockIdx.y == 2) ? w2 : w3;
        out = (blockIdx.y == 0) ? o0 : (blockIdx.y == 1) ? o1 :
              (blockIdx.y == 2) ? o2 : o3;
        n4 = nw4;
    }
    int i = blockIdx.x * blockDim.x + threadIdx.x;
    const int stride = gridDim.x * blockDim.x;
    for (; i < n4; i += stride) {
        float4 v = *(const float4*)(in + (size_t)i * 4);
        uint2 hh; hh.x = packh(v.x, v.y); hh.y = packh(v.z, v.w);
        *(uint2*)(out + (size_t)i * 4) = hh;
    }
}

// ---------------------------------------------------------------------------
// Single-term fp16 GEMM core: CTA 128x128, 8 warps (32x64 warp tile),
// K-tile 64, double buffer (64KB smem), chunk-XOR swizzle.
// ---------------------------------------------------------------------------
#define NT16  16
#define TILEB 16384       // 128 rows * 128B

__device__ __forceinline__ void stage_g(
    uint32_t s, const __half* __restrict__ G, int r0, int koff, int tid)
{
#pragma unroll
    for (int i = 0; i < 4; ++i) {
        int idx = tid + i * 256;
        int r = idx >> 3, c = idx & 7;
        uint32_t sw = r * 128 + ((c ^ (r & 7)) << 4);
        const __half* g = G + (size_t)(r0 + r) * CDIM + koff + c * 8;
        asm volatile("cp.async.cg.shared.global [%0], [%1], 16;"
                     :: "r"(s + sw), "l"(g));
    }
}

__device__ __forceinline__ void gemm_core(
    uint32_t s0, const __half* A16, const __half* B16,
    int m0, int n0, int tid, int lane, int wm, int wn,
    float acc[2][8][4])
{
    uint32_t sA[2] = { s0,             s0 + 2 * TILEB };
    uint32_t sB[2] = { s0 + TILEB,     s0 + 3 * TILEB };

    const int a_r  = wm + (lane & 7) + ((lane >> 3) & 1) * 8;
    const int a_kc = lane >> 4;
    const int b_r  = wn + (lane & 7) + (lane >> 4) * 8;
    const int b_kc = (lane >> 3) & 1;

    stage_g(sA[0], A16, m0, 0, tid);
    stage_g(sB[0], B16, n0, 0, tid);
    asm volatile("cp.async.commit_group;" ::: "memory");

    for (int t = 0; t < NT16; ++t) {
        const int cur = t & 1, nxt = cur ^ 1;
        if (t + 1 < NT16) {
            const int ko = (t + 1) * 64;
            stage_g(sA[nxt], A16, m0, ko, tid);
            stage_g(sB[nxt], B16, n0, ko, tid);
            asm volatile("cp.async.commit_group;" ::: "memory");
            asm volatile("cp.async.wait_group 1;" ::: "memory");
        } else {
            asm volatile("cp.async.wait_group 0;" ::: "memory");
        }
        __syncthreads();

#pragma unroll
        for (int ks = 0; ks < 4; ++ks) {
            uint32_t af[2][4];
#pragma unroll
            for (int mt = 0; mt < 2; ++mt) {
                const int r = a_r + mt * 16;
                uint32_t off = r * 128 + (((ks * 2 + a_kc) ^ (r & 7)) << 4);
                ldsm4(af[mt][0], af[mt][1], af[mt][2], af[mt][3], sA[cur] + off);
            }
            uint32_t bf[8][2];
#pragma unroll
            for (int p = 0; p < 4; ++p) {
                const int r = b_r + p * 16;
                uint32_t off = r * 128 + (((ks * 2 + b_kc) ^ (r & 7)) << 4);
                ldsm4(bf[2 * p][0], bf[2 * p][1], bf[2 * p + 1][0], bf[2 * p + 1][1],
                      sB[cur] + off);
            }
#pragma unroll
            for (int mt = 0; mt < 2; ++mt)
#pragma unroll
                for (int nt = 0; nt < 8; ++nt)
                    mma_f16(acc[mt][nt], af[mt], bf[nt][0], bf[nt][1]);
        }
        __syncthreads();
    }
}

// Fused QKV projection: grid.x = 24 (8 n-blocks x {q,k,v}); fp16 out.
__global__ __launch_bounds__(256) void gemm_qkv(
    const __half* __restrict__ x16,
    const __half* __restrict__ wq16, const __half* __restrict__ wk16,
    const __half* __restrict__ wv16,
    __half* __restrict__ q16, __half* __restrict__ k16, __half* __restrict__ v16,
    const float* __restrict__ cv, const float* __restrict__ cb)
{
    extern __shared__ char gsm[];
    uint32_t s0 = smem_u32(gsm);

    const int tid = threadIdx.x, lane = tid & 31, wid = tid >> 5;
    const int wm = (wid >> 1) * 32, wn = (wid & 1) * 64;
    const int wsel = blockIdx.x >> 3;
    const int n0 = (blockIdx.x & 7) * 128;
    const int m0 = blockIdx.y * 128;

    const __half* B16 = (wsel == 0) ? wq16 : (wsel == 1) ? wk16 : wv16;
    __half* O = (wsel == 0) ? q16 : (wsel == 1) ? k16 : v16;

    float acc[2][8][4];
#pragma unroll
    for (int a = 0; a < 2; ++a)
#pragma unroll
        for (int b = 0; b < 8; ++b)
#pragma unroll
            for (int c = 0; c < 4; ++c) acc[a][b][c] = 0.0f;

    gemm_core(s0, x16, B16, m0, n0, tid, lane, wm, wn, acc);

    const int er = lane >> 2, ec = (lane & 3) * 2;
#pragma unroll
    for (int mt = 0; mt < 2; ++mt)
#pragma unroll
        for (int half = 0; half < 2; ++half) {
            const int row = m0 + wm + mt * 16 + er + half * 8;
#pragma unroll
            for (int nt = 0; nt < 8; ++nt) {
                const int col = n0 + wn + nt * 8 + ec;
                float v0 = acc[mt][nt][half * 2 + 0];
                float v1 = acc[mt][nt][half * 2 + 1];
                if (wsel == 0) {
                    const float* cvr = cv + (size_t)row * CDIM;
                    v0 += cb[col]     * cvr[col];
                    v1 += cb[col + 1] * cvr[col + 1];
                }
                *(uint32_t*)(O + (size_t)row * CDIM + col) = packh(v0, v1);
            }
        }
}

// Output projection: fp32 out + bias
__global__ __launch_bounds__(256) void gemm_out(
    const __half* __restrict__ a16, const __half* __restrict__ wo16,
    float* __restrict__ Y, const float* __restrict__ bias)
{
    extern __shared__ char gsm[];
    uint32_t s0 = smem_u32(gsm);

    const int tid = threadIdx.x, lane = tid & 31, wid = tid >> 5;
    const int wm = (wid >> 1) * 32, wn = (wid & 1) * 64;
    const int m0 = blockIdx.y * 128, n0 = blockIdx.x * 128;

    float acc[2][8][4];
#pragma unroll
    for (int a = 0; a < 2; ++a)
#pragma unroll
        for (int b = 0; b < 8; ++b)
#pragma unroll
            for (int c = 0; c < 4; ++c) acc[a][b][c] = 0.0f;

    gemm_core(s0, a16, wo16, m0, n0, tid, lane, wm, wn, acc);

    const int er = lane >> 2, ec = (lane & 3) * 2;
#pragma unroll
    for (int mt = 0; mt < 2; ++mt)
#pragma unroll
        for (int half = 0; half < 2; ++half) {
            const int row = m0 + wm + mt * 16 + er + half * 8;
            float* yrow = Y + (size_t)row * CDIM;
#pragma unroll
            for (int nt = 0; nt < 8; ++nt) {
                const int col = n0 + wn + nt * 8 + ec;
                float2 f;
                f.x = acc[mt][nt][half * 2 + 0] + bias[col];
                f.y = acc[mt][nt][half * 2 + 1] + bias[col + 1];
                *(float2*)(yrow + col) = f;
            }
        }
}

// ---------------------------------------------------------------------------
// Causal flash attention, pure fp16 mma. CTA: 128 q-rows of one (b,h);
// 8 warps of 16 q-rows x 128 k-cols. K/V double-buffered; heavy tiles first.
// ---------------------------------------------------------------------------
__device__ __forceinline__ void stage_kv(
    uint32_t kvb, const __half* __restrict__ k16, const __half* __restrict__ v16,
    size_t rb, int tid)
{
#pragma unroll
    for (int i = 0; i < 4; ++i) {
        int idx = tid + i * 256;
        int r = idx >> 3, c = idx & 7;
        uint32_t sw = r * 128 + ((c ^ (r & 7)) << 4);
        size_t g = rb + (size_t)r * CDIM + c * 8;
        asm volatile("cp.async.cg.shared.global [%0], [%1], 16;" :: "r"(kvb + sw),         "l"(k16 + g));
        asm volatile("cp.async.cg.shared.global [%0], [%1], 16;" :: "r"(kvb + 16384 + sw), "l"(v16 + g));
    }
    asm volatile("cp.async.commit_group;" ::: "memory");
}

__global__ __launch_bounds__(256) void attn_mma(
    const __half* __restrict__ q16,
    const __half* __restrict__ k16, const __half* __restrict__ v16,
    __half* __restrict__ o16)
{
    extern __shared__ char asmem[];
    const uint32_t s0 = smem_u32(asmem);
    const uint32_t sQ = s0;
    const uint32_t kv0 = s0 + 16384;          // 2 buffers x 32KB: K,V

    const int tid = threadIdx.x, lane = tid & 31, wid = tid >> 5;
    const int qt = (gridDim.x - 1) - blockIdx.x;   // heavy tiles first
    const int bh = blockIdx.y;
    const int b  = bh >> 4, h = bh & 15;
    const float SCL = 0.125f * 1.4426950408889634f;

    const size_t tokbase = (size_t)b * T_SEQ;
    const size_t headoff = (size_t)h * HD;

    // ---- stage Q + K/V tile 0
    {
        const __half* gq = q16 + (tokbase + qt * 128) * CDIM + headoff;
#pragma unroll
        for (int i = 0; i < 4; ++i) {
            int idx = tid + i * 256;
            int r = idx >> 3, c = idx & 7;
            uint32_t sw = r * 128 + ((c ^ (r & 7)) << 4);
            asm volatile("cp.async.cg.shared.global [%0], [%1], 16;"
                         :: "r"(sQ + sw), "l"(gq + (size_t)r * CDIM + c * 8));
        }
    }
    stage_kv(kv0, k16, v16, tokbase * CDIM + headoff, tid);

    uint32_t qf[4][4];
    float o[8][4];
#pragma unroll
    for (int i = 0; i < 8; ++i)
#pragma unroll
        for (int j = 0; j < 4; ++j) o[i][j] = 0.0f;
    float m_[2] = { -1e30f, -1e30f };
    float l_[2] = { 0.0f, 0.0f };

    const int b_rb = (lane & 7) + ((lane >> 4) << 3);
    const int b_kc = (lane >> 3) & 1;
    const int v_rb = (lane & 7) + (((lane >> 3) & 1) << 3);
    const int v_cs = lane >> 4;

    for (int kt = 0; kt <= qt; ++kt) {
        const int cur = kt & 1;
        const uint32_t kvb = kv0 + cur * 32768;
        if (kt < qt) {
            stage_kv(kv0 + (cur ^ 1) * 32768, k16, v16,
                     (tokbase + (size_t)(kt + 1) * 128) * CDIM + headoff, tid);
            asm volatile("cp.async.wait_group 1;" ::: "memory");
        } else {
            asm volatile("cp.async.wait_group 0;" ::: "memory");
        }
        __syncthreads();

        if (kt == 0) {   // Q fragments now resident
            const int a_r  = wid * 16 + (lane & 7) + ((lane >> 3) & 1) * 8;
            const int a_kc = lane >> 4;
#pragma unroll
            for (int ks = 0; ks < 4; ++ks) {
                const int ch = ks * 2 + a_kc;
                uint32_t sw = a_r * 128 + ((ch ^ (a_r & 7)) << 4);
                ldsm4(qf[ks][0], qf[ks][1], qf[ks][2], qf[ks][3], sQ + sw);
            }
        }

        const uint32_t sK = kvb, sV = kvb + 16384;

        // ---- S = Q K^T
        float sc[16][4];
#pragma unroll
        for (int t = 0; t < 16; ++t)
#pragma unroll
            for (int j = 0; j < 4; ++j) sc[t][j] = 0.0f;

#pragma unroll
        for (int ks = 0; ks < 4; ++ks) {
#pragma unroll
            for (int g = 0; g < 8; ++g) {
                const int r = g * 16 + b_rb;
                const int ch = ks * 2 + b_kc;
                uint32_t sw = r * 128 + ((ch ^ (r & 7)) << 4);
                uint32_t k0, k1, k2, k3;
                ldsm4(k0, k1, k2, k3, sK + sw);
                mma_f16(sc[2 * g],     qf[ks], k0, k1);
                mma_f16(sc[2 * g + 1], qf[ks], k2, k3);
            }
        }

        // ---- scale + causal mask (diagonal tile only)
        const bool diag = (kt == qt);
#pragma unroll
        for (int t = 0; t < 16; ++t)
#pragma unroll
            for (int j = 0; j < 4; ++j) {
                float v = sc[t][j] * SCL;
                if (diag) {
                    const int col = t * 8 + ((lane & 3) << 1) + (j & 1);
                    const int row = (wid << 4) + (lane >> 2) + ((j >> 1) << 3);
                    if (col > row) v = -1e30f;
                }
                sc[t][j] = v;
            }

        // ---- online softmax (log2 domain)
#pragma unroll
        for (int hf = 0; hf < 2; ++hf) {
            float mx = -1e30f;
#pragma unroll
            for (int t = 0; t < 16; ++t)
                mx = fmaxf(mx, fmaxf(sc[t][2 * hf], sc[t][2 * hf + 1]));
            mx = fmaxf(mx, __shfl_xor_sync(0xffffffffu, mx, 1));
            mx = fmaxf(mx, __shfl_xor_sync(0xffffffffu, mx, 2));
            const float mn = fmaxf(m_[hf], mx);
            const float corr = ex2f(m_[hf] - mn);
            float rs = 0.0f;
#pragma unroll
            for (int t = 0; t < 16; ++t) {
                float p0 = ex2f(sc[t][2 * hf]     - mn);
                float p1 = ex2f(sc[t][2 * hf + 1] - mn);
                sc[t][2 * hf] = p0; sc[t][2 * hf + 1] = p1;
                rs += p0 + p1;
            }
            rs += __shfl_xor_sync(0xffffffffu, rs, 1);
            rs += __shfl_xor_sync(0xffffffffu, rs, 2);
            l_[hf] = l_[hf] * corr + rs;
            m_[hf] = mn;
#pragma unroll
            for (int nt = 0; nt < 8; ++nt) {
                o[nt][2 * hf]     *= corr;
                o[nt][2 * hf + 1] *= corr;
            }
        }

        // ---- O += P V (P fp16 fragments in registers)
#pragma unroll
        for (int ks2 = 0; ks2 < 8; ++ks2) {
            uint32_t ph[4];
            ph[0] = packh(sc[2 * ks2][0],     sc[2 * ks2][1]);
            ph[1] = packh(sc[2 * ks2][2],     sc[2 * ks2][3]);
            ph[2] = packh(sc[2 * ks2 + 1][0], sc[2 * ks2 + 1][1]);
            ph[3] = packh(sc[2 * ks2 + 1][2], sc[2 * ks2 + 1][3]);
#pragma unroll
            for (int ng = 0; ng < 4; ++ng) {
                const int r = ks2 * 16 + v_rb;
                const int ch = ng * 2 + v_cs;
                uint32_t sw = r * 128 + ((ch ^ (r & 7)) << 4);
                uint32_t v0, v1, v2, v3;
                ldsm4t(v0, v1, v2, v3, sV + sw);
                mma_f16(o[2 * ng],     ph, v0, v1);
                mma_f16(o[2 * ng + 1], ph, v2, v3);
            }
        }
        __syncthreads();
    }

    // ---- epilogue: normalize, store fp16
#pragma unroll
    for (int hf = 0; hf < 2; ++hf) {
        const float inv = 1.0f / l_[hf];
        const int row = qt * 128 + wid * 16 + (lane >> 2) + hf * 8;
        __half* oh = o16 + (tokbase + row) * CDIM + headoff;
#pragma unroll
        for (int nt = 0; nt < 8; ++nt) {
            const int col = nt * 8 + (lane & 3) * 2;
            *(uint32_t*)(oh + col) =
                packh(o[nt][2 * hf] * inv, o[nt][2 * hf + 1] * inv);
        }
    }
}

// ---------------------------------------------------------------------------
// Launch.  Inputs: 0:x 1:mask 2:context_vector 3:w_q 4:w_k 5:w_v 6:w_o 7:b_o
//                  8:context_bias    out: f32 [2,2048,1024]
// ---------------------------------------------------------------------------
extern "C" void kernel_launch(void* const* d_in, const int* in_sizes, int n_in,
                              void* d_out, int out_size)
{
    (void)in_sizes; (void)n_in; (void)out_size;
    const float* x  = (const float*)d_in[0];
    const float* cv = (const float*)d_in[2];
    const float* wq = (const float*)d_in[3];
    const float* wk = (const float*)d_in[4];
    const float* wv = (const float*)d_in[5];
    const float* wo = (const float*)d_in[6];
    const float* bo = (const float*)d_in[7];
    const float* cb = (const float*)d_in[8];
    float* out = (float*)d_out;

    __half *x16, *wq16, *wk16, *wv16, *wo16, *q16, *k16, *v16, *a16;
    cudaGetSymbolAddress((void**)&x16,  g_x16);
    cudaGetSymbolAddress((void**)&wq16, g_wq16);
    cudaGetSymbolAddress((void**)&wk16, g_wk16);
    cudaGetSymbolAddress((void**)&wv16, g_wv16);
    cudaGetSymbolAddress((void**)&wo16, g_wo16);
    cudaGetSymbolAddress((void**)&q16,  g_q16);
    cudaGetSymbolAddress((void**)&k16,  g_k16);
    cudaGetSymbolAddress((void**)&v16,  g_v16);
    cudaGetSymbolAddress((void**)&a16,  g_a16);

    const int gemm_smem = 4 * TILEB;                 // 65536
    cudaFuncSetAttribute(gemm_qkv, cudaFuncAttributeMaxDynamicSharedMemorySize, gemm_smem);
    cudaFuncSetAttribute(gemm_out, cudaFuncAttributeMaxDynamicSharedMemorySize, gemm_smem);
    const int attn_smem = 16384 + 2 * 32768;         // 81920
    cudaFuncSetAttribute(attn_mma, cudaFuncAttributeMaxDynamicSharedMemorySize, attn_smem);

    const int NX4 = MTOK * CDIM / 4;
    const int NW4 = CDIM * CDIM / 4;

    cvt_all<<<dim3(256, 5), 256>>>(x, wq, wk, wv, wo,
                                   x16, wq16, wk16, wv16, wo16, NW4, NX4);

    gemm_qkv<<<dim3(24, MTOK / 128), 256, gemm_smem>>>(
        x16, wq16, wk16, wv16, q16, k16, v16, cv, cb);

    attn_mma<<<dim3(T_SEQ / 128, NB * NH), 256, attn_smem>>>(
        q16, k16, v16, a16);

    gemm_out<<<dim3(CDIM / 128, MTOK / 128), 256, gemm_smem>>>(
        a16, wo16, out, bo);
}